// round 11
// baseline (speedup 1.0000x reference)
#include <cuda_runtime.h>
#include <math.h>

// Problem constants (fixed by the dataset)
#define NNODES 100000
#define HDIM   128
#define NGRAPH 256
#define EMAX   1600000
#define PTILE  64           // rows per GEMM tile
#define ASTRIDE 132         // padded A smem row stride (floats)
#define GEMM_GRID 304       // 2 CTAs/SM on 152-SM GB300
#define GEMM_SMEM (65536 + PTILE * ASTRIDE * 4)

// ---------------- scratch (device globals: allocation-free) ----------------
__device__ float  g_bufA[NNODES * HDIM];
__device__ float  g_bufB[NNODES * HDIM];
__device__ float  g_bufC[NNODES * HDIM];
__device__ float  g_invs[NNODES];
__device__ float  g_pooled[NGRAPH * HDIM];
__device__ int    g_cnt[NNODES];
__device__ int    g_off[NNODES + 1];
__device__ int    g_cursor[NNODES];
__device__ int    g_bsum[1024];
__device__ float2 g_edge[EMAX];   // {__int_as_float(src), invs[src]}

__device__ __forceinline__ unsigned f2tf32(float x) {
    unsigned r;
    asm("cvt.rna.tf32.f32 %0, %1;" : "=r"(r) : "f"(x));
    return r;
}

// ---------------- CSR build ----------------
__global__ void k_zeros(int* cnt, float* pooled, int N, int P) {
    int i = blockIdx.x * blockDim.x + threadIdx.x;
    if (i < N) cnt[i] = 0;
    if (i < P) pooled[i] = 0.f;
}

__global__ void k_hist(const int* __restrict__ dst, int* cnt, int E) {
    int e = blockIdx.x * blockDim.x + threadIdx.x;
    if (e < E) atomicAdd(&cnt[dst[e]], 1);
}

__global__ void k_scan1(const int* __restrict__ cnt, int* __restrict__ off,
                        int* __restrict__ bsum, int n)
{
    __shared__ int sh[1024];
    int i = blockIdx.x * 1024 + threadIdx.x;
    int v = (i < n) ? cnt[i] : 0;
    sh[threadIdx.x] = v;
    __syncthreads();
    #pragma unroll
    for (int ofs = 1; ofs < 1024; ofs <<= 1) {
        int t = (threadIdx.x >= ofs) ? sh[threadIdx.x - ofs] : 0;
        __syncthreads();
        sh[threadIdx.x] += t;
        __syncthreads();
    }
    if (i < n) off[i] = sh[threadIdx.x] - v;
    if (threadIdx.x == 1023) bsum[blockIdx.x] = sh[1023];
}

__global__ void k_scan2(int* bsum, int nb) {
    __shared__ int sh[1024];
    int t = threadIdx.x;
    int v = (t < nb) ? bsum[t] : 0;
    sh[t] = v;
    __syncthreads();
    #pragma unroll
    for (int ofs = 1; ofs < 1024; ofs <<= 1) {
        int u = (t >= ofs) ? sh[t - ofs] : 0;
        __syncthreads();
        sh[t] += u;
        __syncthreads();
    }
    if (t < nb) bsum[t] = sh[t] - v;
}

__global__ void k_scan3_prep(int* __restrict__ off, const int* __restrict__ bsum,
                             const int* __restrict__ cnt, int* __restrict__ cursor,
                             float* __restrict__ invs, int N, int E)
{
    int i = blockIdx.x * 1024 + threadIdx.x;
    if (i < N) {
        int o = off[i] + bsum[blockIdx.x];
        off[i] = o;
        cursor[i] = o;
        invs[i] = rsqrtf((float)(cnt[i] + 1));
    }
    if (i == 0) off[N] = E;
}

__global__ void k_fill(const int* __restrict__ esrc, const int* __restrict__ edst,
                       const float* __restrict__ invs, int* cursor,
                       float2* __restrict__ edge, int E)
{
    int e = blockIdx.x * blockDim.x + threadIdx.x;
    if (e < E) {
        int d = edst[e];
        int s = esrc[e];
        int pos = atomicAdd(&cursor[d], 1);
        edge[pos] = make_float2(__int_as_float(s), invs[s]);
    }
}

// ---------------- persistent tf32 GEMM (round-8, proven 41.8us) ----------------
__global__ void __launch_bounds__(256, 2)
gemm_tf32p(const float* __restrict__ A, const float* __restrict__ W,
           const float* __restrict__ bias, float* __restrict__ C,
           int M, int ntiles, int reluA)
{
    extern __shared__ char smem_raw[];
    uint4* Wf = (uint4*)smem_raw;                    // [16ks][8ntp][32lane] = 64KB
    float* As = (float*)(smem_raw + 65536);          // [PTILE][ASTRIDE]
    const int tid = threadIdx.x;

    auto prefetch = [&](int tileIdx) {
        if (tileIdx < ntiles) {
            int row0 = tileIdx * PTILE;
            #pragma unroll
            for (int j = 0; j < 8; ++j) {
                int cid = tid + 256 * j;
                int row = cid >> 5;
                int c16 = cid & 31;
                const float* gsrc = A + (size_t)(row0 + row) * 128 + c16 * 4;
                float* dptr = As + row * ASTRIDE + c16 * 4;
                unsigned sa = (unsigned)__cvta_generic_to_shared(dptr);
                int sz = (row0 + row < M) ? 16 : 0;
                if (sz == 0) gsrc = A;
                asm volatile("cp.async.ca.shared.global [%0], [%1], 16, %2;"
                             :: "r"(sa), "l"(gsrc), "r"(sz));
            }
        }
        asm volatile("cp.async.commit_group;");
    };

    prefetch(blockIdx.x);

    for (int i = tid * 4; i < 128 * 128; i += 256 * 4) {
        int k = i >> 7, n0 = i & 127;
        float4 v = *(const float4*)(W + i);
        int ks = k >> 3, r = k & 7, reg = r >> 2, tg = r & 3;
        #pragma unroll
        for (int j = 0; j < 4; ++j) {
            int n = n0 + j;
            int nt = n >> 3, gd = n & 7;
            int ntp = nt >> 1, half = nt & 1;
            unsigned* p = (unsigned*)&Wf[(ks * 8 + ntp) * 32 + ((gd << 2) | tg)];
            p[half * 2 + reg] = f2tf32((&v.x)[j]);
        }
    }

    const int warp = tid >> 5;
    const int lane = tid & 31;
    const int gid  = lane >> 2;
    const int tig  = lane & 3;
    const int wm   = warp & 1;
    const int wn   = warp >> 1;

    const int quad = lane >> 3;
    const int qr   = lane & 7;
    unsigned abase[2];
    #pragma unroll
    for (int mi = 0; mi < 2; ++mi) {
        float* p = As + (wm * 32 + mi * 16 + (quad & 1) * 8 + qr) * ASTRIDE + (quad >> 1) * 4;
        abase[mi] = (unsigned)__cvta_generic_to_shared(p);
    }

    for (int tile = blockIdx.x; tile < ntiles; tile += gridDim.x) {
        asm volatile("cp.async.wait_group 0;");
        __syncthreads();

        // ---- in-place relu + tf32 convert of A tile ----
        #pragma unroll
        for (int j = 0; j < 8; ++j) {
            int cid = tid + 256 * j;
            int row = cid >> 5;
            int c16 = cid & 31;
            float4* p = (float4*)(As + row * ASTRIDE + c16 * 4);
            float4 v = *p;
            if (reluA) {
                v.x = fmaxf(v.x, 0.f); v.y = fmaxf(v.y, 0.f);
                v.z = fmaxf(v.z, 0.f); v.w = fmaxf(v.w, 0.f);
            }
            uint4 u;
            u.x = f2tf32(v.x); u.y = f2tf32(v.y); u.z = f2tf32(v.z); u.w = f2tf32(v.w);
            *(uint4*)p = u;
        }
        __syncthreads();

        float acc[2][4][4];
        #pragma unroll
        for (int mi = 0; mi < 2; ++mi)
            #pragma unroll
            for (int t = 0; t < 4; ++t)
                #pragma unroll
                for (int c = 0; c < 4; ++c) acc[mi][t][c] = 0.f;

        #pragma unroll
        for (int ks = 0; ks < 16; ++ks) {
            unsigned au[2][4];
            #pragma unroll
            for (int mi = 0; mi < 2; ++mi) {
                asm volatile(
                    "ldmatrix.sync.aligned.m8n8.x4.shared.b16 {%0,%1,%2,%3}, [%4];"
                    : "=r"(au[mi][0]), "=r"(au[mi][1]), "=r"(au[mi][2]), "=r"(au[mi][3])
                    : "r"(abase[mi] + ks * 32));
            }
            const uint4* Bp = Wf + (ks * 8 + wn * 2) * 32 + lane;
            #pragma unroll
            for (int tp = 0; tp < 2; ++tp) {
                uint4 b4 = Bp[tp * 32];
                #pragma unroll
                for (int mi = 0; mi < 2; ++mi) {
                    asm volatile(
                        "mma.sync.aligned.m16n8k8.row.col.f32.tf32.tf32.f32 "
                        "{%0,%1,%2,%3}, {%4,%5,%6,%7}, {%8,%9}, {%0,%1,%2,%3};"
                        : "+f"(acc[mi][tp * 2][0]), "+f"(acc[mi][tp * 2][1]),
                          "+f"(acc[mi][tp * 2][2]), "+f"(acc[mi][tp * 2][3])
                        : "r"(au[mi][0]), "r"(au[mi][1]), "r"(au[mi][2]), "r"(au[mi][3]),
                          "r"(b4.x), "r"(b4.y));
                    asm volatile(
                        "mma.sync.aligned.m16n8k8.row.col.f32.tf32.tf32.f32 "
                        "{%0,%1,%2,%3}, {%4,%5,%6,%7}, {%8,%9}, {%0,%1,%2,%3};"
                        : "+f"(acc[mi][tp * 2 + 1][0]), "+f"(acc[mi][tp * 2 + 1][1]),
                          "+f"(acc[mi][tp * 2 + 1][2]), "+f"(acc[mi][tp * 2 + 1][3])
                        : "r"(au[mi][0]), "r"(au[mi][1]), "r"(au[mi][2]), "r"(au[mi][3]),
                          "r"(b4.z), "r"(b4.w));
                }
            }
        }

        __syncthreads();
        prefetch(tile + gridDim.x);    // overlap next A load with epilogue

        const int rbase = tile * PTILE + wm * 32;
        #pragma unroll
        for (int mi = 0; mi < 2; ++mi) {
            const int rA = rbase + mi * 16 + gid;
            const int rB = rA + 8;
            #pragma unroll
            for (int t = 0; t < 4; ++t) {
                int n = (wn * 4 + t) * 8 + tig * 2;
                float2 b = *(const float2*)(bias + n);
                if (rA < M)
                    *(float2*)(C + (size_t)rA * 128 + n) =
                        make_float2(acc[mi][t][0] + b.x, acc[mi][t][1] + b.y);
                if (rB < M)
                    *(float2*)(C + (size_t)rB * 128 + n) =
                        make_float2(acc[mi][t][2] + b.x, acc[mi][t][3] + b.y);
            }
        }
    }
}

// ---------------- CSR gather aggregation v4: MLP=8, optional fused pooling ----------------
// out[d,:] = invs[d] * ( hw[d,:]*invs[d] + sum_e hw[src_e,:]*invs[src_e] )
// fusePool: instead of storing out, atomically add result into pooled[batch[d],:]
__global__ void k_aggregate(const float* __restrict__ hw, const float2* __restrict__ edge,
                            const int* __restrict__ off, const float* __restrict__ invs,
                            float* __restrict__ out, const int* __restrict__ batch,
                            float* __restrict__ pooled, int N, int fusePool)
{
    int w = (blockIdx.x * blockDim.x + threadIdx.x) >> 5;
    if (w >= N) return;
    int lane = threadIdx.x & 31;
    int beg = __ldg(off + w), end = __ldg(off + w + 1);
    float invd = __ldg(invs + w);
    const float4* hw4 = (const float4*)hw;

    float4 s = __ldg(hw4 + (size_t)w * 32 + lane);
    float4 a0 = make_float4(s.x * invd, s.y * invd, s.z * invd, s.w * invd);
    float4 a1 = make_float4(0.f, 0.f, 0.f, 0.f);
    float4 a2 = make_float4(0.f, 0.f, 0.f, 0.f);
    float4 a3 = make_float4(0.f, 0.f, 0.f, 0.f);

    int j = beg;
    // 8-deep: 8 independent row loads in flight per warp
    for (; j + 8 <= end; j += 8) {
        float2 e0 = __ldg(edge + j);
        float2 e1 = __ldg(edge + j + 1);
        float2 e2 = __ldg(edge + j + 2);
        float2 e3 = __ldg(edge + j + 3);
        float2 e4 = __ldg(edge + j + 4);
        float2 e5 = __ldg(edge + j + 5);
        float2 e6 = __ldg(edge + j + 6);
        float2 e7 = __ldg(edge + j + 7);
        float4 v0 = __ldg(hw4 + (size_t)__float_as_int(e0.x) * 32 + lane);
        float4 v1 = __ldg(hw4 + (size_t)__float_as_int(e1.x) * 32 + lane);
        float4 v2 = __ldg(hw4 + (size_t)__float_as_int(e2.x) * 32 + lane);
        float4 v3 = __ldg(hw4 + (size_t)__float_as_int(e3.x) * 32 + lane);
        float4 v4 = __ldg(hw4 + (size_t)__float_as_int(e4.x) * 32 + lane);
        float4 v5 = __ldg(hw4 + (size_t)__float_as_int(e5.x) * 32 + lane);
        float4 v6 = __ldg(hw4 + (size_t)__float_as_int(e6.x) * 32 + lane);
        float4 v7 = __ldg(hw4 + (size_t)__float_as_int(e7.x) * 32 + lane);
        a0.x = fmaf(v0.x, e0.y, a0.x); a0.y = fmaf(v0.y, e0.y, a0.y);
        a0.z = fmaf(v0.z, e0.y, a0.z); a0.w = fmaf(v0.w, e0.y, a0.w);
        a1.x = fmaf(v1.x, e1.y, a1.x); a1.y = fmaf(v1.y, e1.y, a1.y);
        a1.z = fmaf(v1.z, e1.y, a1.z); a1.w = fmaf(v1.w, e1.y, a1.w);
        a2.x = fmaf(v2.x, e2.y, a2.x); a2.y = fmaf(v2.y, e2.y, a2.y);
        a2.z = fmaf(v2.z, e2.y, a2.z); a2.w = fmaf(v2.w, e2.y, a2.w);
        a3.x = fmaf(v3.x, e3.y, a3.x); a3.y = fmaf(v3.y, e3.y, a3.y);
        a3.z = fmaf(v3.z, e3.y, a3.z); a3.w = fmaf(v3.w, e3.y, a3.w);
        a0.x = fmaf(v4.x, e4.y, a0.x); a0.y = fmaf(v4.y, e4.y, a0.y);
        a0.z = fmaf(v4.z, e4.y, a0.z); a0.w = fmaf(v4.w, e4.y, a0.w);
        a1.x = fmaf(v5.x, e5.y, a1.x); a1.y = fmaf(v5.y, e5.y, a1.y);
        a1.z = fmaf(v5.z, e5.y, a1.z); a1.w = fmaf(v5.w, e5.y, a1.w);
        a2.x = fmaf(v6.x, e6.y, a2.x); a2.y = fmaf(v6.y, e6.y, a2.y);
        a2.z = fmaf(v6.z, e6.y, a2.z); a2.w = fmaf(v6.w, e6.y, a2.w);
        a3.x = fmaf(v7.x, e7.y, a3.x); a3.y = fmaf(v7.y, e7.y, a3.y);
        a3.z = fmaf(v7.z, e7.y, a3.z); a3.w = fmaf(v7.w, e7.y, a3.w);
    }
    for (; j + 4 <= end; j += 4) {
        float2 e0 = __ldg(edge + j);
        float2 e1 = __ldg(edge + j + 1);
        float2 e2 = __ldg(edge + j + 2);
        float2 e3 = __ldg(edge + j + 3);
        float4 v0 = __ldg(hw4 + (size_t)__float_as_int(e0.x) * 32 + lane);
        float4 v1 = __ldg(hw4 + (size_t)__float_as_int(e1.x) * 32 + lane);
        float4 v2 = __ldg(hw4 + (size_t)__float_as_int(e2.x) * 32 + lane);
        float4 v3 = __ldg(hw4 + (size_t)__float_as_int(e3.x) * 32 + lane);
        a0.x = fmaf(v0.x, e0.y, a0.x); a0.y = fmaf(v0.y, e0.y, a0.y);
        a0.z = fmaf(v0.z, e0.y, a0.z); a0.w = fmaf(v0.w, e0.y, a0.w);
        a1.x = fmaf(v1.x, e1.y, a1.x); a1.y = fmaf(v1.y, e1.y, a1.y);
        a1.z = fmaf(v1.z, e1.y, a1.z); a1.w = fmaf(v1.w, e1.y, a1.w);
        a2.x = fmaf(v2.x, e2.y, a2.x); a2.y = fmaf(v2.y, e2.y, a2.y);
        a2.z = fmaf(v2.z, e2.y, a2.z); a2.w = fmaf(v2.w, e2.y, a2.w);
        a3.x = fmaf(v3.x, e3.y, a3.x); a3.y = fmaf(v3.y, e3.y, a3.y);
        a3.z = fmaf(v3.z, e3.y, a3.z); a3.w = fmaf(v3.w, e3.y, a3.w);
    }
    for (; j < end; ++j) {
        float2 e0 = __ldg(edge + j);
        float4 v0 = __ldg(hw4 + (size_t)__float_as_int(e0.x) * 32 + lane);
        a0.x = fmaf(v0.x, e0.y, a0.x); a0.y = fmaf(v0.y, e0.y, a0.y);
        a0.z = fmaf(v0.z, e0.y, a0.z); a0.w = fmaf(v0.w, e0.y, a0.w);
    }

    float4 o;
    o.x = ((a0.x + a1.x) + (a2.x + a3.x)) * invd;
    o.y = ((a0.y + a1.y) + (a2.y + a3.y)) * invd;
    o.z = ((a0.z + a1.z) + (a2.z + a3.z)) * invd;
    o.w = ((a0.w + a1.w) + (a2.w + a3.w)) * invd;

    if (fusePool) {
        int g = __ldg(batch + w);
        float* p = pooled + (size_t)g * 128 + lane * 4;
        asm volatile("red.global.add.v4.f32 [%0], {%1,%2,%3,%4};"
                     :: "l"(p), "f"(o.x), "f"(o.y), "f"(o.z), "f"(o.w)
                     : "memory");
    } else {
        ((float4*)out)[(size_t)w * 32 + lane] = o;
    }
}

// ---------------- decoder ----------------
__global__ void k_decoder(const float* __restrict__ pooled,
                          const float* __restrict__ w1, const float* __restrict__ b1,
                          const float* __restrict__ w2, const float* __restrict__ b2,
                          float* __restrict__ out)
{
    __shared__ float p[128];
    __shared__ float d1[128];
    int g = blockIdx.x;
    int t = threadIdx.x;
    p[t] = pooled[g * 128 + t];
    __syncthreads();
    float s = b1[t];
    #pragma unroll 8
    for (int k = 0; k < 128; ++k) s = fmaf(p[k], w1[k * 128 + t], s);
    d1[t] = fmaxf(s, 0.f);
    __syncthreads();
    if (t < 10) {
        float s2 = b2[t];
        #pragma unroll 8
        for (int j = 0; j < 128; ++j) s2 = fmaf(d1[j], w2[j * 10 + t], s2);
        out[g * 10 + t] = s2;
    }
}

// ---------------- driver ----------------
extern "C" void kernel_launch(void* const* d_in, const int* in_sizes, int n_in,
                              void* d_out, int out_size)
{
    const float* x      = (const float*)d_in[0];
    const int*   ei     = (const int*)d_in[1];
    const int*   batch  = (const int*)d_in[3];
    const float* enc_w1 = (const float*)d_in[4];
    const float* enc_b1 = (const float*)d_in[5];
    const float* enc_w2 = (const float*)d_in[6];
    const float* enc_b2 = (const float*)d_in[7];
    const float* conv_w = (const float*)d_in[8];
    const float* conv_b = (const float*)d_in[9];
    const float* dec_w1 = (const float*)d_in[10];
    const float* dec_b1 = (const float*)d_in[11];
    const float* dec_w2 = (const float*)d_in[12];
    const float* dec_b2 = (const float*)d_in[13];

    const int N = in_sizes[0] / HDIM;
    const int E = in_sizes[1] / 2;
    const int G = out_size / 10;

    float *bufA, *bufB, *bufC, *invs, *pooled;
    int *cnt, *off, *cursor, *bsum;
    float2* edge;
    cudaGetSymbolAddress((void**)&bufA, g_bufA);
    cudaGetSymbolAddress((void**)&bufB, g_bufB);
    cudaGetSymbolAddress((void**)&bufC, g_bufC);
    cudaGetSymbolAddress((void**)&invs, g_invs);
    cudaGetSymbolAddress((void**)&pooled, g_pooled);
    cudaGetSymbolAddress((void**)&cnt, g_cnt);
    cudaGetSymbolAddress((void**)&off, g_off);
    cudaGetSymbolAddress((void**)&cursor, g_cursor);
    cudaGetSymbolAddress((void**)&bsum, g_bsum);
    cudaGetSymbolAddress((void**)&edge, g_edge);

    const int* esrc = ei;
    const int* edst = ei + E;
    const int nb = (N + 1023) / 1024;
    const int ntiles = (N + PTILE - 1) / PTILE;

    cudaFuncSetAttribute(gemm_tf32p, cudaFuncAttributeMaxDynamicSharedMemorySize, GEMM_SMEM);

    // launches 0..2 (CSR head)
    k_zeros<<<(N + 255) / 256, 256>>>(cnt, pooled, N, G * 128);
    k_hist<<<(E + 255) / 256, 256>>>(edst, cnt, E);
    k_scan1<<<nb, 1024>>>(cnt, off, bsum, N);

    // launch 3: encoder GEMM 1  (profiled slot)
    gemm_tf32p<<<GEMM_GRID, 256, GEMM_SMEM>>>(x, enc_w1, enc_b1, bufC, N, ntiles, 0);

    // launches 4..5 (CSR tail)
    k_scan2<<<1, 1024>>>(bsum, nb);
    k_scan3_prep<<<nb, 1024>>>(off, bsum, cnt, cursor, invs, N, E);

    // encoder GEMM 2
    gemm_tf32p<<<GEMM_GRID, 256, GEMM_SMEM>>>(bufC, enc_w2, enc_b2, bufA, N, ntiles, 1);

    // edge records (needs invs)
    k_fill<<<(E + 255) / 256, 256>>>(esrc, edst, invs, cursor, edge, E);

    float* hcur  = bufA;
    float* hnext = bufC;
    float* hw    = bufB;

    for (int l = 0; l < 3; ++l) {
        gemm_tf32p<<<GEMM_GRID, 256, GEMM_SMEM>>>(hcur, conv_w + (size_t)l * 128 * 128,
                                                  conv_b + (size_t)l * 128, hw, N, ntiles,
                                                  l > 0 ? 1 : 0);
        int fuse = (l == 2) ? 1 : 0;   // last layer: aggregate straight into pooled
        k_aggregate<<<(N * 32 + 255) / 256, 256>>>(hw, edge, off, invs, hnext,
                                                   batch, pooled, N, fuse);
        float* t = hcur; hcur = hnext; hnext = t;
    }

    // decoder (pooled filled by fused last aggregate; zeroed at launch 0)
    k_decoder<<<G, 128>>>(pooled, dec_w1, dec_b1, dec_w2, dec_b2, (float*)d_out);
}

// round 12
// speedup vs baseline: 1.1820x; 1.1820x over previous
#include <cuda_runtime.h>
#include <math.h>

// Problem constants (fixed by the dataset)
#define NNODES 100000
#define HDIM   128
#define NGRAPH 256
#define EMAX   1600000
#define PTILE  64           // rows per GEMM tile
#define ASTRIDE 132         // padded A smem row stride (floats)
#define GEMM_GRID 304       // 2 CTAs/SM on 152-SM GB300
#define GEMM_SMEM (65536 + PTILE * ASTRIDE * 4)

// ---------------- scratch (device globals: allocation-free) ----------------
__device__ float  g_bufA[NNODES * HDIM];
__device__ float  g_bufB[NNODES * HDIM];
__device__ float  g_bufC[NNODES * HDIM];
__device__ float  g_invs[NNODES];
__device__ float  g_srow[NNODES];
__device__ float  g_pooled[NGRAPH * HDIM];
__device__ float  g_poolscal[NGRAPH];
__device__ float  g_wfold[HDIM * HDIM];
__device__ float  g_bfold[HDIM];
__device__ int    g_cnt[NNODES];
__device__ int    g_off[NNODES + 1];
__device__ int    g_cursor[NNODES];
__device__ int    g_bsum[1024];
__device__ float2 g_edge[EMAX];   // {__int_as_float(src), invs[src]}

__device__ __forceinline__ unsigned f2tf32(float x) {
    unsigned r;
    asm("cvt.rna.tf32.f32 %0, %1;" : "=r"(r) : "f"(x));
    return r;
}

// ---------------- CSR build ----------------
__global__ void k_zeros(int* cnt, float* pooled, float* poolscal, int N, int P, int G) {
    int i = blockIdx.x * blockDim.x + threadIdx.x;
    if (i < N) cnt[i] = 0;
    if (i < P) pooled[i] = 0.f;
    if (i < G) poolscal[i] = 0.f;
}

__global__ void k_hist(const int* __restrict__ dst, int* cnt, int E) {
    int e = blockIdx.x * blockDim.x + threadIdx.x;
    if (e < E) atomicAdd(&cnt[dst[e]], 1);
}

__global__ void k_scan1(const int* __restrict__ cnt, int* __restrict__ off,
                        int* __restrict__ bsum, int n)
{
    __shared__ int sh[1024];
    int i = blockIdx.x * 1024 + threadIdx.x;
    int v = (i < n) ? cnt[i] : 0;
    sh[threadIdx.x] = v;
    __syncthreads();
    #pragma unroll
    for (int ofs = 1; ofs < 1024; ofs <<= 1) {
        int t = (threadIdx.x >= ofs) ? sh[threadIdx.x - ofs] : 0;
        __syncthreads();
        sh[threadIdx.x] += t;
        __syncthreads();
    }
    if (i < n) off[i] = sh[threadIdx.x] - v;
    if (threadIdx.x == 1023) bsum[blockIdx.x] = sh[1023];
}

__global__ void k_scan2(int* bsum, int nb) {
    __shared__ int sh[1024];
    int t = threadIdx.x;
    int v = (t < nb) ? bsum[t] : 0;
    sh[t] = v;
    __syncthreads();
    #pragma unroll
    for (int ofs = 1; ofs < 1024; ofs <<= 1) {
        int u = (t >= ofs) ? sh[t - ofs] : 0;
        __syncthreads();
        sh[t] += u;
        __syncthreads();
    }
    if (t < nb) bsum[t] = sh[t] - v;
}

__global__ void k_scan3_prep(int* __restrict__ off, const int* __restrict__ bsum,
                             const int* __restrict__ cnt, int* __restrict__ cursor,
                             float* __restrict__ invs, int N, int E)
{
    int i = blockIdx.x * 1024 + threadIdx.x;
    if (i < N) {
        int o = off[i] + bsum[blockIdx.x];
        off[i] = o;
        cursor[i] = o;
        invs[i] = rsqrtf((float)(cnt[i] + 1));
    }
    if (i == 0) off[N] = E;
}

__global__ void k_fill(const int* __restrict__ esrc, const int* __restrict__ edst,
                       const float* __restrict__ invs, int* cursor,
                       float2* __restrict__ edge, int E)
{
    int e = blockIdx.x * blockDim.x + threadIdx.x;
    if (e < E) {
        int d = edst[e];
        int s = esrc[e];
        int pos = atomicAdd(&cursor[d], 1);
        edge[pos] = make_float2(__int_as_float(s), invs[s]);
    }
}

// ---------------- weight folds (conv0 into encoder-gemm2) ----------------
// wfold[k][n] = sum_j enc_w2[k][j] * cw0[j][n]
__global__ void k_wfold(const float* __restrict__ w2, const float* __restrict__ cw0,
                        float* __restrict__ wf)
{
    __shared__ float row[128];
    int k = blockIdx.x, n = threadIdx.x;
    row[n] = w2[k * 128 + n];
    __syncthreads();
    float acc = 0.f;
    #pragma unroll 8
    for (int j = 0; j < 128; ++j) acc = fmaf(row[j], cw0[j * 128 + n], acc);
    wf[k * 128 + n] = acc;
}

// bfold[n] = sum_j enc_b2[j] * cw0[j][n] + cb0[n]
__global__ void k_bfold(const float* __restrict__ b2, const float* __restrict__ cw0,
                        const float* __restrict__ cb0, float* __restrict__ bf)
{
    int n = threadIdx.x;
    float acc = cb0[n];
    #pragma unroll 8
    for (int j = 0; j < 128; ++j) acc = fmaf(b2[j], cw0[j * 128 + n], acc);
    bf[n] = acc;
}

// ---------------- persistent tf32 GEMM (round-8, proven 41.8us) ----------------
__global__ void __launch_bounds__(256, 2)
gemm_tf32p(const float* __restrict__ A, const float* __restrict__ W,
           const float* __restrict__ bias, float* __restrict__ C,
           int M, int ntiles, int reluA)
{
    extern __shared__ char smem_raw[];
    uint4* Wf = (uint4*)smem_raw;                    // [16ks][8ntp][32lane] = 64KB
    float* As = (float*)(smem_raw + 65536);          // [PTILE][ASTRIDE]
    const int tid = threadIdx.x;

    auto prefetch = [&](int tileIdx) {
        if (tileIdx < ntiles) {
            int row0 = tileIdx * PTILE;
            #pragma unroll
            for (int j = 0; j < 8; ++j) {
                int cid = tid + 256 * j;
                int row = cid >> 5;
                int c16 = cid & 31;
                const float* gsrc = A + (size_t)(row0 + row) * 128 + c16 * 4;
                float* dptr = As + row * ASTRIDE + c16 * 4;
                unsigned sa = (unsigned)__cvta_generic_to_shared(dptr);
                int sz = (row0 + row < M) ? 16 : 0;
                if (sz == 0) gsrc = A;
                asm volatile("cp.async.ca.shared.global [%0], [%1], 16, %2;"
                             :: "r"(sa), "l"(gsrc), "r"(sz));
            }
        }
        asm volatile("cp.async.commit_group;");
    };

    prefetch(blockIdx.x);

    for (int i = tid * 4; i < 128 * 128; i += 256 * 4) {
        int k = i >> 7, n0 = i & 127;
        float4 v = *(const float4*)(W + i);
        int ks = k >> 3, r = k & 7, reg = r >> 2, tg = r & 3;
        #pragma unroll
        for (int j = 0; j < 4; ++j) {
            int n = n0 + j;
            int nt = n >> 3, gd = n & 7;
            int ntp = nt >> 1, half = nt & 1;
            unsigned* p = (unsigned*)&Wf[(ks * 8 + ntp) * 32 + ((gd << 2) | tg)];
            p[half * 2 + reg] = f2tf32((&v.x)[j]);
        }
    }

    const int warp = tid >> 5;
    const int lane = tid & 31;
    const int gid  = lane >> 2;
    const int tig  = lane & 3;
    const int wm   = warp & 1;
    const int wn   = warp >> 1;

    const int quad = lane >> 3;
    const int qr   = lane & 7;
    unsigned abase[2];
    #pragma unroll
    for (int mi = 0; mi < 2; ++mi) {
        float* p = As + (wm * 32 + mi * 16 + (quad & 1) * 8 + qr) * ASTRIDE + (quad >> 1) * 4;
        abase[mi] = (unsigned)__cvta_generic_to_shared(p);
    }

    for (int tile = blockIdx.x; tile < ntiles; tile += gridDim.x) {
        asm volatile("cp.async.wait_group 0;");
        __syncthreads();

        #pragma unroll
        for (int j = 0; j < 8; ++j) {
            int cid = tid + 256 * j;
            int row = cid >> 5;
            int c16 = cid & 31;
            float4* p = (float4*)(As + row * ASTRIDE + c16 * 4);
            float4 v = *p;
            if (reluA) {
                v.x = fmaxf(v.x, 0.f); v.y = fmaxf(v.y, 0.f);
                v.z = fmaxf(v.z, 0.f); v.w = fmaxf(v.w, 0.f);
            }
            uint4 u;
            u.x = f2tf32(v.x); u.y = f2tf32(v.y); u.z = f2tf32(v.z); u.w = f2tf32(v.w);
            *(uint4*)p = u;
        }
        __syncthreads();

        float acc[2][4][4];
        #pragma unroll
        for (int mi = 0; mi < 2; ++mi)
            #pragma unroll
            for (int t = 0; t < 4; ++t)
                #pragma unroll
                for (int c = 0; c < 4; ++c) acc[mi][t][c] = 0.f;

        #pragma unroll
        for (int ks = 0; ks < 16; ++ks) {
            unsigned au[2][4];
            #pragma unroll
            for (int mi = 0; mi < 2; ++mi) {
                asm volatile(
                    "ldmatrix.sync.aligned.m8n8.x4.shared.b16 {%0,%1,%2,%3}, [%4];"
                    : "=r"(au[mi][0]), "=r"(au[mi][1]), "=r"(au[mi][2]), "=r"(au[mi][3])
                    : "r"(abase[mi] + ks * 32));
            }
            const uint4* Bp = Wf + (ks * 8 + wn * 2) * 32 + lane;
            #pragma unroll
            for (int tp = 0; tp < 2; ++tp) {
                uint4 b4 = Bp[tp * 32];
                #pragma unroll
                for (int mi = 0; mi < 2; ++mi) {
                    asm volatile(
                        "mma.sync.aligned.m16n8k8.row.col.f32.tf32.tf32.f32 "
                        "{%0,%1,%2,%3}, {%4,%5,%6,%7}, {%8,%9}, {%0,%1,%2,%3};"
                        : "+f"(acc[mi][tp * 2][0]), "+f"(acc[mi][tp * 2][1]),
                          "+f"(acc[mi][tp * 2][2]), "+f"(acc[mi][tp * 2][3])
                        : "r"(au[mi][0]), "r"(au[mi][1]), "r"(au[mi][2]), "r"(au[mi][3]),
                          "r"(b4.x), "r"(b4.y));
                    asm volatile(
                        "mma.sync.aligned.m16n8k8.row.col.f32.tf32.tf32.f32 "
                        "{%0,%1,%2,%3}, {%4,%5,%6,%7}, {%8,%9}, {%0,%1,%2,%3};"
                        : "+f"(acc[mi][tp * 2 + 1][0]), "+f"(acc[mi][tp * 2 + 1][1]),
                          "+f"(acc[mi][tp * 2 + 1][2]), "+f"(acc[mi][tp * 2 + 1][3])
                        : "r"(au[mi][0]), "r"(au[mi][1]), "r"(au[mi][2]), "r"(au[mi][3]),
                          "r"(b4.z), "r"(b4.w));
                }
            }
        }

        __syncthreads();
        prefetch(tile + gridDim.x);

        const int rbase = tile * PTILE + wm * 32;
        #pragma unroll
        for (int mi = 0; mi < 2; ++mi) {
            const int rA = rbase + mi * 16 + gid;
            const int rB = rA + 8;
            #pragma unroll
            for (int t = 0; t < 4; ++t) {
                int n = (wn * 4 + t) * 8 + tig * 2;
                float2 b = *(const float2*)(bias + n);
                if (rA < M)
                    *(float2*)(C + (size_t)rA * 128 + n) =
                        make_float2(acc[mi][t][0] + b.x, acc[mi][t][1] + b.y);
                if (rB < M)
                    *(float2*)(C + (size_t)rB * 128 + n) =
                        make_float2(acc[mi][t][2] + b.x, acc[mi][t][3] + b.y);
            }
        }
    }
}

// ---------------- CSR gather aggregation (round-8 body, optional relu at store) ----------------
__global__ void k_aggregate(const float* __restrict__ hw, const float2* __restrict__ edge,
                            const int* __restrict__ off, const float* __restrict__ invs,
                            float* __restrict__ out, int N, int reluStore)
{
    int w = (blockIdx.x * blockDim.x + threadIdx.x) >> 5;
    if (w >= N) return;
    int lane = threadIdx.x & 31;
    int beg = __ldg(off + w), end = __ldg(off + w + 1);
    float invd = __ldg(invs + w);
    const float4* hw4 = (const float4*)hw;

    float4 s = __ldg(hw4 + (size_t)w * 32 + lane);
    float4 a0 = make_float4(s.x * invd, s.y * invd, s.z * invd, s.w * invd);
    float4 a1 = make_float4(0.f, 0.f, 0.f, 0.f);
    float4 a2 = make_float4(0.f, 0.f, 0.f, 0.f);
    float4 a3 = make_float4(0.f, 0.f, 0.f, 0.f);

    int j = beg;
    for (; j + 4 <= end; j += 4) {
        float2 e0 = __ldg(edge + j);
        float2 e1 = __ldg(edge + j + 1);
        float2 e2 = __ldg(edge + j + 2);
        float2 e3 = __ldg(edge + j + 3);
        float4 v0 = __ldg(hw4 + (size_t)__float_as_int(e0.x) * 32 + lane);
        float4 v1 = __ldg(hw4 + (size_t)__float_as_int(e1.x) * 32 + lane);
        float4 v2 = __ldg(hw4 + (size_t)__float_as_int(e2.x) * 32 + lane);
        float4 v3 = __ldg(hw4 + (size_t)__float_as_int(e3.x) * 32 + lane);
        a0.x = fmaf(v0.x, e0.y, a0.x); a0.y = fmaf(v0.y, e0.y, a0.y);
        a0.z = fmaf(v0.z, e0.y, a0.z); a0.w = fmaf(v0.w, e0.y, a0.w);
        a1.x = fmaf(v1.x, e1.y, a1.x); a1.y = fmaf(v1.y, e1.y, a1.y);
        a1.z = fmaf(v1.z, e1.y, a1.z); a1.w = fmaf(v1.w, e1.y, a1.w);
        a2.x = fmaf(v2.x, e2.y, a2.x); a2.y = fmaf(v2.y, e2.y, a2.y);
        a2.z = fmaf(v2.z, e2.y, a2.z); a2.w = fmaf(v2.w, e2.y, a2.w);
        a3.x = fmaf(v3.x, e3.y, a3.x); a3.y = fmaf(v3.y, e3.y, a3.y);
        a3.z = fmaf(v3.z, e3.y, a3.z); a3.w = fmaf(v3.w, e3.y, a3.w);
    }
    for (; j < end; ++j) {
        float2 e0 = __ldg(edge + j);
        float4 v0 = __ldg(hw4 + (size_t)__float_as_int(e0.x) * 32 + lane);
        a0.x = fmaf(v0.x, e0.y, a0.x); a0.y = fmaf(v0.y, e0.y, a0.y);
        a0.z = fmaf(v0.z, e0.y, a0.z); a0.w = fmaf(v0.w, e0.y, a0.w);
    }

    float4 o;
    o.x = ((a0.x + a1.x) + (a2.x + a3.x)) * invd;
    o.y = ((a0.y + a1.y) + (a2.y + a3.y)) * invd;
    o.z = ((a0.z + a1.z) + (a2.z + a3.z)) * invd;
    o.w = ((a0.w + a1.w) + (a2.w + a3.w)) * invd;
    if (reluStore) {
        o.x = fmaxf(o.x, 0.f); o.y = fmaxf(o.y, 0.f);
        o.z = fmaxf(o.z, 0.f); o.w = fmaxf(o.w, 0.f);
    }
    ((float4*)out)[(size_t)w * 32 + lane] = o;
}

// ---------------- last-layer aggregate: also emits srow[d] = invd*(invd + sum e.y) ----------------
__global__ void k_aggregate2(const float* __restrict__ hw, const float2* __restrict__ edge,
                             const int* __restrict__ off, const float* __restrict__ invs,
                             float* __restrict__ out, float* __restrict__ srow, int N)
{
    int w = (blockIdx.x * blockDim.x + threadIdx.x) >> 5;
    if (w >= N) return;
    int lane = threadIdx.x & 31;
    int beg = __ldg(off + w), end = __ldg(off + w + 1);
    float invd = __ldg(invs + w);
    const float4* hw4 = (const float4*)hw;

    float4 s = __ldg(hw4 + (size_t)w * 32 + lane);
    float4 a0 = make_float4(s.x * invd, s.y * invd, s.z * invd, s.w * invd);
    float4 a1 = make_float4(0.f, 0.f, 0.f, 0.f);
    float4 a2 = make_float4(0.f, 0.f, 0.f, 0.f);
    float4 a3 = make_float4(0.f, 0.f, 0.f, 0.f);
    float esum = 0.f;

    int j = beg;
    for (; j + 4 <= end; j += 4) {
        float2 e0 = __ldg(edge + j);
        float2 e1 = __ldg(edge + j + 1);
        float2 e2 = __ldg(edge + j + 2);
        float2 e3 = __ldg(edge + j + 3);
        float4 v0 = __ldg(hw4 + (size_t)__float_as_int(e0.x) * 32 + lane);
        float4 v1 = __ldg(hw4 + (size_t)__float_as_int(e1.x) * 32 + lane);
        float4 v2 = __ldg(hw4 + (size_t)__float_as_int(e2.x) * 32 + lane);
        float4 v3 = __ldg(hw4 + (size_t)__float_as_int(e3.x) * 32 + lane);
        esum += (e0.y + e1.y) + (e2.y + e3.y);
        a0.x = fmaf(v0.x, e0.y, a0.x); a0.y = fmaf(v0.y, e0.y, a0.y);
        a0.z = fmaf(v0.z, e0.y, a0.z); a0.w = fmaf(v0.w, e0.y, a0.w);
        a1.x = fmaf(v1.x, e1.y, a1.x); a1.y = fmaf(v1.y, e1.y, a1.y);
        a1.z = fmaf(v1.z, e1.y, a1.z); a1.w = fmaf(v1.w, e1.y, a1.w);
        a2.x = fmaf(v2.x, e2.y, a2.x); a2.y = fmaf(v2.y, e2.y, a2.y);
        a2.z = fmaf(v2.z, e2.y, a2.z); a2.w = fmaf(v2.w, e2.y, a2.w);
        a3.x = fmaf(v3.x, e3.y, a3.x); a3.y = fmaf(v3.y, e3.y, a3.y);
        a3.z = fmaf(v3.z, e3.y, a3.z); a3.w = fmaf(v3.w, e3.y, a3.w);
    }
    for (; j < end; ++j) {
        float2 e0 = __ldg(edge + j);
        float4 v0 = __ldg(hw4 + (size_t)__float_as_int(e0.x) * 32 + lane);
        esum += e0.y;
        a0.x = fmaf(v0.x, e0.y, a0.x); a0.y = fmaf(v0.y, e0.y, a0.y);
        a0.z = fmaf(v0.z, e0.y, a0.z); a0.w = fmaf(v0.w, e0.y, a0.w);
    }

    float4 o;
    o.x = ((a0.x + a1.x) + (a2.x + a3.x)) * invd;
    o.y = ((a0.y + a1.y) + (a2.y + a3.y)) * invd;
    o.z = ((a0.z + a1.z) + (a2.z + a3.z)) * invd;
    o.w = ((a0.w + a1.w) + (a2.w + a3.w)) * invd;
    ((float4*)out)[(size_t)w * 32 + lane] = o;
    if (lane == 0) srow[w] = invd * (invd + esum);
}

// ---------------- pooling (rows + scalar) ----------------
__global__ void k_pool2(const float* __restrict__ h, const float* __restrict__ srow,
                        const int* __restrict__ batch, float* __restrict__ pooled,
                        float* __restrict__ poolscal, int N)
{
    int w = (blockIdx.x * blockDim.x + threadIdx.x) >> 5;
    if (w >= N) return;
    int lane = threadIdx.x & 31;
    int g = __ldg(batch + w);
    float4 v = *(const float4*)(h + (size_t)w * 128 + lane * 4);
    float* p = pooled + (size_t)g * 128 + lane * 4;
    asm volatile("red.global.add.v4.f32 [%0], {%1,%2,%3,%4};"
                 :: "l"(p), "f"(v.x), "f"(v.y), "f"(v.z), "f"(v.w)
                 : "memory");
    if (lane == 0) {
        float sv = __ldg(srow + w);
        asm volatile("red.global.add.f32 [%0], %1;"
                     :: "l"(poolscal + g), "f"(sv) : "memory");
    }
}

// ---------------- decoder with folded conv2 ----------------
// pf = pooledY @ cw2 + poolscal*cb2 ; out = relu(pf@dw1+db1)@dw2 + db2
__global__ void k_decoder2(const float* __restrict__ pooledY, const float* __restrict__ poolscal,
                           const float* __restrict__ cw2, const float* __restrict__ cb2,
                           const float* __restrict__ w1, const float* __restrict__ b1,
                           const float* __restrict__ w2, const float* __restrict__ b2,
                           float* __restrict__ out)
{
    __shared__ float pY[128];
    __shared__ float p[128];
    __shared__ float d1[128];
    int g = blockIdx.x;
    int t = threadIdx.x;
    pY[t] = pooledY[g * 128 + t];
    __syncthreads();
    float ps = poolscal[g];
    float acc = ps * cb2[t];
    #pragma unroll 8
    for (int j = 0; j < 128; ++j) acc = fmaf(pY[j], cw2[j * 128 + t], acc);
    p[t] = acc;
    __syncthreads();
    float s = b1[t];
    #pragma unroll 8
    for (int k = 0; k < 128; ++k) s = fmaf(p[k], w1[k * 128 + t], s);
    d1[t] = fmaxf(s, 0.f);
    __syncthreads();
    if (t < 10) {
        float s2 = b2[t];
        #pragma unroll 8
        for (int j = 0; j < 128; ++j) s2 = fmaf(d1[j], w2[j * 10 + t], s2);
        out[g * 10 + t] = s2;
    }
}

// ---------------- driver ----------------
extern "C" void kernel_launch(void* const* d_in, const int* in_sizes, int n_in,
                              void* d_out, int out_size)
{
    const float* x      = (const float*)d_in[0];
    const int*   ei     = (const int*)d_in[1];
    const int*   batch  = (const int*)d_in[3];
    const float* enc_w1 = (const float*)d_in[4];
    const float* enc_b1 = (const float*)d_in[5];
    const float* enc_w2 = (const float*)d_in[6];
    const float* enc_b2 = (const float*)d_in[7];
    const float* conv_w = (const float*)d_in[8];
    const float* conv_b = (const float*)d_in[9];
    const float* dec_w1 = (const float*)d_in[10];
    const float* dec_b1 = (const float*)d_in[11];
    const float* dec_w2 = (const float*)d_in[12];
    const float* dec_b2 = (const float*)d_in[13];

    const int N = in_sizes[0] / HDIM;
    const int E = in_sizes[1] / 2;
    const int G = out_size / 10;

    float *bufA, *bufB, *bufC, *invs, *srow, *pooled, *poolscal, *wfold, *bfold;
    int *cnt, *off, *cursor, *bsum;
    float2* edge;
    cudaGetSymbolAddress((void**)&bufA, g_bufA);
    cudaGetSymbolAddress((void**)&bufB, g_bufB);
    cudaGetSymbolAddress((void**)&bufC, g_bufC);
    cudaGetSymbolAddress((void**)&invs, g_invs);
    cudaGetSymbolAddress((void**)&srow, g_srow);
    cudaGetSymbolAddress((void**)&pooled, g_pooled);
    cudaGetSymbolAddress((void**)&poolscal, g_poolscal);
    cudaGetSymbolAddress((void**)&wfold, g_wfold);
    cudaGetSymbolAddress((void**)&bfold, g_bfold);
    cudaGetSymbolAddress((void**)&cnt, g_cnt);
    cudaGetSymbolAddress((void**)&off, g_off);
    cudaGetSymbolAddress((void**)&cursor, g_cursor);
    cudaGetSymbolAddress((void**)&bsum, g_bsum);
    cudaGetSymbolAddress((void**)&edge, g_edge);

    const int* esrc = ei;
    const int* edst = ei + E;
    const int nb = (N + 1023) / 1024;
    const int ntiles = (N + PTILE - 1) / PTILE;

    const float* cw0 = conv_w;
    const float* cw1 = conv_w + 128 * 128;
    const float* cw2 = conv_w + 2 * 128 * 128;
    const float* cb0 = conv_b;
    const float* cb1 = conv_b + 128;
    const float* cb2 = conv_b + 2 * 128;

    cudaFuncSetAttribute(gemm_tf32p, cudaFuncAttributeMaxDynamicSharedMemorySize, GEMM_SMEM);

    // launches 0..2 (CSR head)
    k_zeros<<<(N + 255) / 256, 256>>>(cnt, pooled, poolscal, N, G * 128, G);
    k_hist<<<(E + 255) / 256, 256>>>(edst, cnt, E);
    k_scan1<<<nb, 1024>>>(cnt, off, bsum, N);

    // launch 3: encoder GEMM 1  (profiled slot)
    gemm_tf32p<<<GEMM_GRID, 256, GEMM_SMEM>>>(x, enc_w1, enc_b1, bufC, N, ntiles, 0);

    // CSR tail + weight folds
    k_scan2<<<1, 1024>>>(bsum, nb);
    k_scan3_prep<<<nb, 1024>>>(off, bsum, cnt, cursor, invs, N, E);
    k_wfold<<<128, 128>>>(enc_w2, cw0, wfold);
    k_bfold<<<1, 128>>>(enc_b2, cw0, cb0, bfold);
    k_fill<<<(E + 255) / 256, 256>>>(esrc, edst, invs, cursor, edge, E);

    // encoder GEMM2 with conv0 folded in: hw0 = relu(bufC)@wfold + bfold
    gemm_tf32p<<<GEMM_GRID, 256, GEMM_SMEM>>>(bufC, wfold, bfold, bufB, N, ntiles, 1);

    // layer 0 aggregate: h1_pre = Â hw0
    k_aggregate<<<(N * 32 + 255) / 256, 256>>>(bufB, edge, off, invs, bufA, N, 0);

    // layer 1: hw1 = relu(h1_pre)@cw1 + cb1 ; h2 = relu(Â hw1)
    gemm_tf32p<<<GEMM_GRID, 256, GEMM_SMEM>>>(bufA, cw1, cb1, bufB, N, ntiles, 1);
    k_aggregate<<<(N * 32 + 255) / 256, 256>>>(bufB, edge, off, invs, bufC, N, 1);

    // layer 2 folded: aggY = Â h2, srow ; pool both
    k_aggregate2<<<(N * 32 + 255) / 256, 256>>>(bufC, edge, off, invs, bufA, srow, N);
    k_pool2<<<(N * 32 + 255) / 256, 256>>>(bufA, srow, batch, pooled, poolscal, N);

    // decoder with pf = pooled@cw2 + poolscal*cb2
    k_decoder2<<<G, 128>>>(pooled, poolscal, cw2, cb2,
                           dec_w1, dec_b1, dec_w2, dec_b2, (float*)d_out);
}

// round 13
// speedup vs baseline: 1.1966x; 1.0124x over previous
#include <cuda_runtime.h>
#include <math.h>

// Problem constants (fixed by the dataset)
#define NNODES 100000
#define HDIM   128
#define NGRAPH 256
#define EMAX   1600000
#define PTILE  64           // rows per GEMM tile
#define ASTRIDE 132         // padded A smem row stride (floats)
#define GEMM_GRID 304       // 2 CTAs/SM on 152-SM GB300
#define GEMM_SMEM (65536 + PTILE * ASTRIDE * 4)

// ---------------- scratch (device globals: allocation-free) ----------------
__device__ float  g_bufA[NNODES * HDIM];
__device__ float  g_bufB[NNODES * HDIM];
__device__ float  g_bufC[NNODES * HDIM];
__device__ float  g_invs[NNODES];
__device__ float  g_srow[NNODES];
__device__ float  g_pooled[NGRAPH * HDIM];
__device__ float  g_poolscal[NGRAPH];
__device__ float  g_wfold[HDIM * HDIM];
__device__ float  g_bfold[HDIM];
__device__ int    g_cnt[NNODES];
__device__ int    g_off[NNODES + 1];
__device__ int    g_cursor[NNODES];
__device__ int    g_bsum[1024];
__device__ float2 g_edge[EMAX];   // {__int_as_float(src), invs[src]}

__device__ __forceinline__ unsigned f2tf32(float x) {
    unsigned r;
    asm("cvt.rna.tf32.f32 %0, %1;" : "=r"(r) : "f"(x));
    return r;
}

// ---------------- CSR build ----------------
__global__ void k_zeros(int* cnt, float* pooled, float* poolscal, int N, int P, int G) {
    int i = blockIdx.x * blockDim.x + threadIdx.x;
    if (i < N) cnt[i] = 0;
    if (i < P) pooled[i] = 0.f;
    if (i < G) poolscal[i] = 0.f;
}

__global__ void k_hist(const int* __restrict__ dst, int* cnt, int E) {
    int e = blockIdx.x * blockDim.x + threadIdx.x;
    if (e < E) atomicAdd(&cnt[dst[e]], 1);
}

__global__ void k_scan1(const int* __restrict__ cnt, int* __restrict__ off,
                        int* __restrict__ bsum, int n)
{
    __shared__ int sh[1024];
    int i = blockIdx.x * 1024 + threadIdx.x;
    int v = (i < n) ? cnt[i] : 0;
    sh[threadIdx.x] = v;
    __syncthreads();
    #pragma unroll
    for (int ofs = 1; ofs < 1024; ofs <<= 1) {
        int t = (threadIdx.x >= ofs) ? sh[threadIdx.x - ofs] : 0;
        __syncthreads();
        sh[threadIdx.x] += t;
        __syncthreads();
    }
    if (i < n) off[i] = sh[threadIdx.x] - v;
    if (threadIdx.x == 1023) bsum[blockIdx.x] = sh[1023];
}

__global__ void k_scan2(int* bsum, int nb) {
    __shared__ int sh[1024];
    int t = threadIdx.x;
    int v = (t < nb) ? bsum[t] : 0;
    sh[t] = v;
    __syncthreads();
    #pragma unroll
    for (int ofs = 1; ofs < 1024; ofs <<= 1) {
        int u = (t >= ofs) ? sh[t - ofs] : 0;
        __syncthreads();
        sh[t] += u;
        __syncthreads();
    }
    if (t < nb) bsum[t] = sh[t] - v;
}

__global__ void k_scan3_prep(int* __restrict__ off, const int* __restrict__ bsum,
                             const int* __restrict__ cnt, int* __restrict__ cursor,
                             float* __restrict__ invs, int N, int E)
{
    int i = blockIdx.x * 1024 + threadIdx.x;
    if (i < N) {
        int o = off[i] + bsum[blockIdx.x];
        off[i] = o;
        cursor[i] = o;
        invs[i] = rsqrtf((float)(cnt[i] + 1));
    }
    if (i == 0) off[N] = E;
}

__global__ void k_fill(const int* __restrict__ esrc, const int* __restrict__ edst,
                       const float* __restrict__ invs, int* cursor,
                       float2* __restrict__ edge, int E)
{
    int e = blockIdx.x * blockDim.x + threadIdx.x;
    if (e < E) {
        int d = edst[e];
        int s = esrc[e];
        int pos = atomicAdd(&cursor[d], 1);
        edge[pos] = make_float2(__int_as_float(s), invs[s]);
    }
}

// ---------------- weight folds (conv0 into encoder-gemm2) ----------------
__global__ void k_wfold(const float* __restrict__ w2, const float* __restrict__ cw0,
                        float* __restrict__ wf)
{
    __shared__ float row[128];
    int k = blockIdx.x, n = threadIdx.x;
    row[n] = w2[k * 128 + n];
    __syncthreads();
    float acc = 0.f;
    #pragma unroll 8
    for (int j = 0; j < 128; ++j) acc = fmaf(row[j], cw0[j * 128 + n], acc);
    wf[k * 128 + n] = acc;
}

__global__ void k_bfold(const float* __restrict__ b2, const float* __restrict__ cw0,
                        const float* __restrict__ cb0, float* __restrict__ bf)
{
    int n = threadIdx.x;
    float acc = cb0[n];
    #pragma unroll 8
    for (int j = 0; j < 128; ++j) acc = fmaf(b2[j], cw0[j * 128 + n], acc);
    bf[n] = acc;
}

// ---------------- persistent tf32 GEMM (round-8, proven) ----------------
__global__ void __launch_bounds__(256, 2)
gemm_tf32p(const float* __restrict__ A, const float* __restrict__ W,
           const float* __restrict__ bias, float* __restrict__ C,
           int M, int ntiles, int reluA)
{
    extern __shared__ char smem_raw[];
    uint4* Wf = (uint4*)smem_raw;                    // [16ks][8ntp][32lane] = 64KB
    float* As = (float*)(smem_raw + 65536);          // [PTILE][ASTRIDE]
    const int tid = threadIdx.x;

    auto prefetch = [&](int tileIdx) {
        if (tileIdx < ntiles) {
            int row0 = tileIdx * PTILE;
            #pragma unroll
            for (int j = 0; j < 8; ++j) {
                int cid = tid + 256 * j;
                int row = cid >> 5;
                int c16 = cid & 31;
                const float* gsrc = A + (size_t)(row0 + row) * 128 + c16 * 4;
                float* dptr = As + row * ASTRIDE + c16 * 4;
                unsigned sa = (unsigned)__cvta_generic_to_shared(dptr);
                int sz = (row0 + row < M) ? 16 : 0;
                if (sz == 0) gsrc = A;
                asm volatile("cp.async.ca.shared.global [%0], [%1], 16, %2;"
                             :: "r"(sa), "l"(gsrc), "r"(sz));
            }
        }
        asm volatile("cp.async.commit_group;");
    };

    prefetch(blockIdx.x);

    for (int i = tid * 4; i < 128 * 128; i += 256 * 4) {
        int k = i >> 7, n0 = i & 127;
        float4 v = *(const float4*)(W + i);
        int ks = k >> 3, r = k & 7, reg = r >> 2, tg = r & 3;
        #pragma unroll
        for (int j = 0; j < 4; ++j) {
            int n = n0 + j;
            int nt = n >> 3, gd = n & 7;
            int ntp = nt >> 1, half = nt & 1;
            unsigned* p = (unsigned*)&Wf[(ks * 8 + ntp) * 32 + ((gd << 2) | tg)];
            p[half * 2 + reg] = f2tf32((&v.x)[j]);
        }
    }

    const int warp = tid >> 5;
    const int lane = tid & 31;
    const int gid  = lane >> 2;
    const int tig  = lane & 3;
    const int wm   = warp & 1;
    const int wn   = warp >> 1;

    const int quad = lane >> 3;
    const int qr   = lane & 7;
    unsigned abase[2];
    #pragma unroll
    for (int mi = 0; mi < 2; ++mi) {
        float* p = As + (wm * 32 + mi * 16 + (quad & 1) * 8 + qr) * ASTRIDE + (quad >> 1) * 4;
        abase[mi] = (unsigned)__cvta_generic_to_shared(p);
    }

    for (int tile = blockIdx.x; tile < ntiles; tile += gridDim.x) {
        asm volatile("cp.async.wait_group 0;");
        __syncthreads();

        #pragma unroll
        for (int j = 0; j < 8; ++j) {
            int cid = tid + 256 * j;
            int row = cid >> 5;
            int c16 = cid & 31;
            float4* p = (float4*)(As + row * ASTRIDE + c16 * 4);
            float4 v = *p;
            if (reluA) {
                v.x = fmaxf(v.x, 0.f); v.y = fmaxf(v.y, 0.f);
                v.z = fmaxf(v.z, 0.f); v.w = fmaxf(v.w, 0.f);
            }
            uint4 u;
            u.x = f2tf32(v.x); u.y = f2tf32(v.y); u.z = f2tf32(v.z); u.w = f2tf32(v.w);
            *(uint4*)p = u;
        }
        __syncthreads();

        float acc[2][4][4];
        #pragma unroll
        for (int mi = 0; mi < 2; ++mi)
            #pragma unroll
            for (int t = 0; t < 4; ++t)
                #pragma unroll
                for (int c = 0; c < 4; ++c) acc[mi][t][c] = 0.f;

        #pragma unroll
        for (int ks = 0; ks < 16; ++ks) {
            unsigned au[2][4];
            #pragma unroll
            for (int mi = 0; mi < 2; ++mi) {
                asm volatile(
                    "ldmatrix.sync.aligned.m8n8.x4.shared.b16 {%0,%1,%2,%3}, [%4];"
                    : "=r"(au[mi][0]), "=r"(au[mi][1]), "=r"(au[mi][2]), "=r"(au[mi][3])
                    : "r"(abase[mi] + ks * 32));
            }
            const uint4* Bp = Wf + (ks * 8 + wn * 2) * 32 + lane;
            #pragma unroll
            for (int tp = 0; tp < 2; ++tp) {
                uint4 b4 = Bp[tp * 32];
                #pragma unroll
                for (int mi = 0; mi < 2; ++mi) {
                    asm volatile(
                        "mma.sync.aligned.m16n8k8.row.col.f32.tf32.tf32.f32 "
                        "{%0,%1,%2,%3}, {%4,%5,%6,%7}, {%8,%9}, {%0,%1,%2,%3};"
                        : "+f"(acc[mi][tp * 2][0]), "+f"(acc[mi][tp * 2][1]),
                          "+f"(acc[mi][tp * 2][2]), "+f"(acc[mi][tp * 2][3])
                        : "r"(au[mi][0]), "r"(au[mi][1]), "r"(au[mi][2]), "r"(au[mi][3]),
                          "r"(b4.x), "r"(b4.y));
                    asm volatile(
                        "mma.sync.aligned.m16n8k8.row.col.f32.tf32.tf32.f32 "
                        "{%0,%1,%2,%3}, {%4,%5,%6,%7}, {%8,%9}, {%0,%1,%2,%3};"
                        : "+f"(acc[mi][tp * 2 + 1][0]), "+f"(acc[mi][tp * 2 + 1][1]),
                          "+f"(acc[mi][tp * 2 + 1][2]), "+f"(acc[mi][tp * 2 + 1][3])
                        : "r"(au[mi][0]), "r"(au[mi][1]), "r"(au[mi][2]), "r"(au[mi][3]),
                          "r"(b4.z), "r"(b4.w));
                }
            }
        }

        __syncthreads();
        prefetch(tile + gridDim.x);

        const int rbase = tile * PTILE + wm * 32;
        #pragma unroll
        for (int mi = 0; mi < 2; ++mi) {
            const int rA = rbase + mi * 16 + gid;
            const int rB = rA + 8;
            #pragma unroll
            for (int t = 0; t < 4; ++t) {
                int n = (wn * 4 + t) * 8 + tig * 2;
                float2 b = *(const float2*)(bias + n);
                if (rA < M)
                    *(float2*)(C + (size_t)rA * 128 + n) =
                        make_float2(acc[mi][t][0] + b.x, acc[mi][t][1] + b.y);
                if (rB < M)
                    *(float2*)(C + (size_t)rB * 128 + n) =
                        make_float2(acc[mi][t][2] + b.x, acc[mi][t][3] + b.y);
            }
        }
    }
}

// ---------------- CSR gather aggregation (round-8 body, optional relu at store) ----------------
__global__ void k_aggregate(const float* __restrict__ hw, const float2* __restrict__ edge,
                            const int* __restrict__ off, const float* __restrict__ invs,
                            float* __restrict__ out, int N, int reluStore)
{
    int w = (blockIdx.x * blockDim.x + threadIdx.x) >> 5;
    if (w >= N) return;
    int lane = threadIdx.x & 31;
    int beg = __ldg(off + w), end = __ldg(off + w + 1);
    float invd = __ldg(invs + w);
    const float4* hw4 = (const float4*)hw;

    float4 s = __ldg(hw4 + (size_t)w * 32 + lane);
    float4 a0 = make_float4(s.x * invd, s.y * invd, s.z * invd, s.w * invd);
    float4 a1 = make_float4(0.f, 0.f, 0.f, 0.f);
    float4 a2 = make_float4(0.f, 0.f, 0.f, 0.f);
    float4 a3 = make_float4(0.f, 0.f, 0.f, 0.f);

    int j = beg;
    for (; j + 4 <= end; j += 4) {
        float2 e0 = __ldg(edge + j);
        float2 e1 = __ldg(edge + j + 1);
        float2 e2 = __ldg(edge + j + 2);
        float2 e3 = __ldg(edge + j + 3);
        float4 v0 = __ldg(hw4 + (size_t)__float_as_int(e0.x) * 32 + lane);
        float4 v1 = __ldg(hw4 + (size_t)__float_as_int(e1.x) * 32 + lane);
        float4 v2 = __ldg(hw4 + (size_t)__float_as_int(e2.x) * 32 + lane);
        float4 v3 = __ldg(hw4 + (size_t)__float_as_int(e3.x) * 32 + lane);
        a0.x = fmaf(v0.x, e0.y, a0.x); a0.y = fmaf(v0.y, e0.y, a0.y);
        a0.z = fmaf(v0.z, e0.y, a0.z); a0.w = fmaf(v0.w, e0.y, a0.w);
        a1.x = fmaf(v1.x, e1.y, a1.x); a1.y = fmaf(v1.y, e1.y, a1.y);
        a1.z = fmaf(v1.z, e1.y, a1.z); a1.w = fmaf(v1.w, e1.y, a1.w);
        a2.x = fmaf(v2.x, e2.y, a2.x); a2.y = fmaf(v2.y, e2.y, a2.y);
        a2.z = fmaf(v2.z, e2.y, a2.z); a2.w = fmaf(v2.w, e2.y, a2.w);
        a3.x = fmaf(v3.x, e3.y, a3.x); a3.y = fmaf(v3.y, e3.y, a3.y);
        a3.z = fmaf(v3.z, e3.y, a3.z); a3.w = fmaf(v3.w, e3.y, a3.w);
    }
    for (; j < end; ++j) {
        float2 e0 = __ldg(edge + j);
        float4 v0 = __ldg(hw4 + (size_t)__float_as_int(e0.x) * 32 + lane);
        a0.x = fmaf(v0.x, e0.y, a0.x); a0.y = fmaf(v0.y, e0.y, a0.y);
        a0.z = fmaf(v0.z, e0.y, a0.z); a0.w = fmaf(v0.w, e0.y, a0.w);
    }

    float4 o;
    o.x = ((a0.x + a1.x) + (a2.x + a3.x)) * invd;
    o.y = ((a0.y + a1.y) + (a2.y + a3.y)) * invd;
    o.z = ((a0.z + a1.z) + (a2.z + a3.z)) * invd;
    o.w = ((a0.w + a1.w) + (a2.w + a3.w)) * invd;
    if (reluStore) {
        o.x = fmaxf(o.x, 0.f); o.y = fmaxf(o.y, 0.f);
        o.z = fmaxf(o.z, 0.f); o.w = fmaxf(o.w, 0.f);
    }
    ((float4*)out)[(size_t)w * 32 + lane] = o;
}

// ---------------- last-layer aggregate: also emits srow[d] = invd*(invd + sum e.y) ----------------
__global__ void k_aggregate2(const float* __restrict__ hw, const float2* __restrict__ edge,
                             const int* __restrict__ off, const float* __restrict__ invs,
                             float* __restrict__ out, float* __restrict__ srow, int N)
{
    int w = (blockIdx.x * blockDim.x + threadIdx.x) >> 5;
    if (w >= N) return;
    int lane = threadIdx.x & 31;
    int beg = __ldg(off + w), end = __ldg(off + w + 1);
    float invd = __ldg(invs + w);
    const float4* hw4 = (const float4*)hw;

    float4 s = __ldg(hw4 + (size_t)w * 32 + lane);
    float4 a0 = make_float4(s.x * invd, s.y * invd, s.z * invd, s.w * invd);
    float4 a1 = make_float4(0.f, 0.f, 0.f, 0.f);
    float4 a2 = make_float4(0.f, 0.f, 0.f, 0.f);
    float4 a3 = make_float4(0.f, 0.f, 0.f, 0.f);
    float esum = 0.f;

    int j = beg;
    for (; j + 4 <= end; j += 4) {
        float2 e0 = __ldg(edge + j);
        float2 e1 = __ldg(edge + j + 1);
        float2 e2 = __ldg(edge + j + 2);
        float2 e3 = __ldg(edge + j + 3);
        float4 v0 = __ldg(hw4 + (size_t)__float_as_int(e0.x) * 32 + lane);
        float4 v1 = __ldg(hw4 + (size_t)__float_as_int(e1.x) * 32 + lane);
        float4 v2 = __ldg(hw4 + (size_t)__float_as_int(e2.x) * 32 + lane);
        float4 v3 = __ldg(hw4 + (size_t)__float_as_int(e3.x) * 32 + lane);
        esum += (e0.y + e1.y) + (e2.y + e3.y);
        a0.x = fmaf(v0.x, e0.y, a0.x); a0.y = fmaf(v0.y, e0.y, a0.y);
        a0.z = fmaf(v0.z, e0.y, a0.z); a0.w = fmaf(v0.w, e0.y, a0.w);
        a1.x = fmaf(v1.x, e1.y, a1.x); a1.y = fmaf(v1.y, e1.y, a1.y);
        a1.z = fmaf(v1.z, e1.y, a1.z); a1.w = fmaf(v1.w, e1.y, a1.w);
        a2.x = fmaf(v2.x, e2.y, a2.x); a2.y = fmaf(v2.y, e2.y, a2.y);
        a2.z = fmaf(v2.z, e2.y, a2.z); a2.w = fmaf(v2.w, e2.y, a2.w);
        a3.x = fmaf(v3.x, e3.y, a3.x); a3.y = fmaf(v3.y, e3.y, a3.y);
        a3.z = fmaf(v3.z, e3.y, a3.z); a3.w = fmaf(v3.w, e3.y, a3.w);
    }
    for (; j < end; ++j) {
        float2 e0 = __ldg(edge + j);
        float4 v0 = __ldg(hw4 + (size_t)__float_as_int(e0.x) * 32 + lane);
        esum += e0.y;
        a0.x = fmaf(v0.x, e0.y, a0.x); a0.y = fmaf(v0.y, e0.y, a0.y);
        a0.z = fmaf(v0.z, e0.y, a0.z); a0.w = fmaf(v0.w, e0.y, a0.w);
    }

    float4 o;
    o.x = ((a0.x + a1.x) + (a2.x + a3.x)) * invd;
    o.y = ((a0.y + a1.y) + (a2.y + a3.y)) * invd;
    o.z = ((a0.z + a1.z) + (a2.z + a3.z)) * invd;
    o.w = ((a0.w + a1.w) + (a2.w + a3.w)) * invd;
    ((float4*)out)[(size_t)w * 32 + lane] = o;
    if (lane == 0) srow[w] = invd * (invd + esum);
}

// ---------------- pooling (rows + scalar) ----------------
__global__ void k_pool2(const float* __restrict__ h, const float* __restrict__ srow,
                        const int* __restrict__ batch, float* __restrict__ pooled,
                        float* __restrict__ poolscal, int N)
{
    int w = (blockIdx.x * blockDim.x + threadIdx.x) >> 5;
    if (w >= N) return;
    int lane = threadIdx.x & 31;
    int g = __ldg(batch + w);
    float4 v = *(const float4*)(h + (size_t)w * 128 + lane * 4);
    float* p = pooled + (size_t)g * 128 + lane * 4;
    asm volatile("red.global.add.v4.f32 [%0], {%1,%2,%3,%4};"
                 :: "l"(p), "f"(v.x), "f"(v.y), "f"(v.z), "f"(v.w)
                 : "memory");
    if (lane == 0) {
        float sv = __ldg(srow + w);
        asm volatile("red.global.add.f32 [%0], %1;"
                     :: "l"(poolscal + g), "f"(sv) : "memory");
    }
}

// ---------------- decoder with folded conv2 ----------------
__global__ void k_decoder2(const float* __restrict__ pooledY, const float* __restrict__ poolscal,
                           const float* __restrict__ cw2, const float* __restrict__ cb2,
                           const float* __restrict__ w1, const float* __restrict__ b1,
                           const float* __restrict__ w2, const float* __restrict__ b2,
                           float* __restrict__ out)
{
    __shared__ float pY[128];
    __shared__ float p[128];
    __shared__ float d1[128];
    int g = blockIdx.x;
    int t = threadIdx.x;
    pY[t] = pooledY[g * 128 + t];
    __syncthreads();
    float ps = poolscal[g];
    float acc = ps * cb2[t];
    #pragma unroll 8
    for (int j = 0; j < 128; ++j) acc = fmaf(pY[j], cw2[j * 128 + t], acc);
    p[t] = acc;
    __syncthreads();
    float s = b1[t];
    #pragma unroll 8
    for (int k = 0; k < 128; ++k) s = fmaf(p[k], w1[k * 128 + t], s);
    d1[t] = fmaxf(s, 0.f);
    __syncthreads();
    if (t < 10) {
        float s2 = b2[t];
        #pragma unroll 8
        for (int j = 0; j < 128; ++j) s2 = fmaf(d1[j], w2[j * 10 + t], s2);
        out[g * 10 + t] = s2;
    }
}

// ---------------- driver: forked graph (CSR chain overlaps encoder GEMMs) ----------------
extern "C" void kernel_launch(void* const* d_in, const int* in_sizes, int n_in,
                              void* d_out, int out_size)
{
    const float* x      = (const float*)d_in[0];
    const int*   ei     = (const int*)d_in[1];
    const int*   batch  = (const int*)d_in[3];
    const float* enc_w1 = (const float*)d_in[4];
    const float* enc_b1 = (const float*)d_in[5];
    const float* enc_w2 = (const float*)d_in[6];
    const float* enc_b2 = (const float*)d_in[7];
    const float* conv_w = (const float*)d_in[8];
    const float* conv_b = (const float*)d_in[9];
    const float* dec_w1 = (const float*)d_in[10];
    const float* dec_b1 = (const float*)d_in[11];
    const float* dec_w2 = (const float*)d_in[12];
    const float* dec_b2 = (const float*)d_in[13];

    const int N = in_sizes[0] / HDIM;
    const int E = in_sizes[1] / 2;
    const int G = out_size / 10;

    float *bufA, *bufB, *bufC, *invs, *srow, *pooled, *poolscal, *wfold, *bfold;
    int *cnt, *off, *cursor, *bsum;
    float2* edge;
    cudaGetSymbolAddress((void**)&bufA, g_bufA);
    cudaGetSymbolAddress((void**)&bufB, g_bufB);
    cudaGetSymbolAddress((void**)&bufC, g_bufC);
    cudaGetSymbolAddress((void**)&invs, g_invs);
    cudaGetSymbolAddress((void**)&srow, g_srow);
    cudaGetSymbolAddress((void**)&pooled, g_pooled);
    cudaGetSymbolAddress((void**)&poolscal, g_poolscal);
    cudaGetSymbolAddress((void**)&wfold, g_wfold);
    cudaGetSymbolAddress((void**)&bfold, g_bfold);
    cudaGetSymbolAddress((void**)&cnt, g_cnt);
    cudaGetSymbolAddress((void**)&off, g_off);
    cudaGetSymbolAddress((void**)&cursor, g_cursor);
    cudaGetSymbolAddress((void**)&bsum, g_bsum);
    cudaGetSymbolAddress((void**)&edge, g_edge);

    const int* esrc = ei;
    const int* edst = ei + E;
    const int nb = (N + 1023) / 1024;
    const int ntiles = (N + PTILE - 1) / PTILE;

    const float* cw0 = conv_w;
    const float* cw1 = conv_w + 128 * 128;
    const float* cw2 = conv_w + 2 * 128 * 128;
    const float* cb0 = conv_b;
    const float* cb1 = conv_b + 128;
    const float* cb2 = conv_b + 2 * 128;

    cudaFuncSetAttribute(gemm_tf32p, cudaFuncAttributeMaxDynamicSharedMemorySize, GEMM_SMEM);

    // side stream + fork/join events (host-side resources only; leaked — kernel_launch
    // runs a handful of times, graph replays don't re-enter)
    cudaStream_t s2;
    cudaStreamCreateWithFlags(&s2, cudaStreamNonBlocking);
    cudaEvent_t evRoot, evW, evCSR;
    cudaEventCreateWithFlags(&evRoot, cudaEventDisableTiming);
    cudaEventCreateWithFlags(&evW, cudaEventDisableTiming);
    cudaEventCreateWithFlags(&evCSR, cudaEventDisableTiming);

    // fork s2 off the main (capture) stream
    cudaEventRecord(evRoot, 0);
    cudaStreamWaitEvent(s2, evRoot, 0);

    // ---- s2: CSR build + weight folds (independent of encoder GEMMs) ----
    k_zeros<<<(N + 255) / 256, 256, 0, s2>>>(cnt, pooled, poolscal, N, G * 128, G);
    k_hist<<<(E + 255) / 256, 256, 0, s2>>>(edst, cnt, E);
    k_scan1<<<nb, 1024, 0, s2>>>(cnt, off, bsum, N);
    k_scan2<<<1, 1024, 0, s2>>>(bsum, nb);
    k_scan3_prep<<<nb, 1024, 0, s2>>>(off, bsum, cnt, cursor, invs, N, E);
    k_wfold<<<128, 128, 0, s2>>>(enc_w2, cw0, wfold);
    k_bfold<<<1, 128, 0, s2>>>(enc_b2, cw0, cb0, bfold);
    cudaEventRecord(evW, s2);               // wfold/bfold ready (GEMM2 gate)
    k_fill<<<(E + 255) / 256, 256, 0, s2>>>(esrc, edst, invs, cursor, edge, E);
    cudaEventRecord(evCSR, s2);             // edge list ready (aggregate gate)

    // ---- main stream: encoder GEMM1 runs concurrently with the CSR chain ----
    gemm_tf32p<<<GEMM_GRID, 256, GEMM_SMEM>>>(x, enc_w1, enc_b1, bufC, N, ntiles, 0);

    // encoder GEMM2 with conv0 folded: hw0 = relu(bufC)@wfold + bfold (overlaps k_fill)
    cudaStreamWaitEvent(0, evW, 0);
    gemm_tf32p<<<GEMM_GRID, 256, GEMM_SMEM>>>(bufC, wfold, bfold, bufB, N, ntiles, 1);

    // join: aggregates need edge/off/invs
    cudaStreamWaitEvent(0, evCSR, 0);

    // layer 0 aggregate: h1_pre = Â hw0
    k_aggregate<<<(N * 32 + 255) / 256, 256>>>(bufB, edge, off, invs, bufA, N, 0);

    // layer 1: hw1 = relu(h1_pre)@cw1 + cb1 ; h2 = relu(Â hw1)
    gemm_tf32p<<<GEMM_GRID, 256, GEMM_SMEM>>>(bufA, cw1, cb1, bufB, N, ntiles, 1);
    k_aggregate<<<(N * 32 + 255) / 256, 256>>>(bufB, edge, off, invs, bufC, N, 1);

    // layer 2 folded: aggY = Â h2, srow ; pool both
    k_aggregate2<<<(N * 32 + 255) / 256, 256>>>(bufC, edge, off, invs, bufA, srow, N);
    k_pool2<<<(N * 32 + 255) / 256, 256>>>(bufA, srow, batch, pooled, poolscal, N);

    // decoder with pf = pooled@cw2 + poolscal*cb2
    k_decoder2<<<G, 128>>>(pooled, poolscal, cw2, cb2,
                           dec_w1, dec_b1, dec_w2, dec_b2, (float*)d_out);
}

// round 15
// speedup vs baseline: 1.2724x; 1.0633x over previous
#include <cuda_runtime.h>
#include <math.h>

// Problem constants (fixed by the dataset)
#define NNODES 100000
#define HDIM   128
#define NGRAPH 256
#define EMAX   1600000
#define PTILE  64           // rows per GEMM tile
#define ASTRIDE 132         // padded A smem row stride (floats)
#define GEMM_GRID 304       // 2 CTAs/SM on 152-SM GB300
#define GEMM_SMEM (65536 + PTILE * ASTRIDE * 4)

// ---------------- scratch (device globals: allocation-free) ----------------
__device__ float  g_bufA[NNODES * HDIM];
__device__ float  g_bufB[NNODES * HDIM];
__device__ float  g_bufC[NNODES * HDIM];
__device__ float  g_invs[NNODES];
__device__ float  g_pooled[NGRAPH * HDIM];
__device__ float  g_poolscal[NGRAPH];
__device__ float  g_wfold[HDIM * HDIM];
__device__ float  g_bfold[HDIM];
__device__ int    g_cnt[NNODES];
__device__ int    g_off[NNODES + 1];
__device__ int    g_cursor[NNODES];
__device__ int    g_bsum[1024];
__device__ float2 g_edge[EMAX];   // {__int_as_float(src), invs[src]}

__device__ __forceinline__ unsigned f2tf32(float x) {
    unsigned r;
    asm("cvt.rna.tf32.f32 %0, %1;" : "=r"(r) : "f"(x));
    return r;
}

// ---------------- CSR build ----------------
__global__ void k_zeros(int* cnt, float* pooled, float* poolscal, int N, int P, int G) {
    int i = blockIdx.x * blockDim.x + threadIdx.x;
    if (i < N) cnt[i] = 0;
    if (i < P) pooled[i] = 0.f;
    if (i < G) poolscal[i] = 0.f;
}

__global__ void k_hist(const int* __restrict__ dst, int* cnt, int E) {
    int e = blockIdx.x * blockDim.x + threadIdx.x;
    if (e < E) atomicAdd(&cnt[dst[e]], 1);
}

__global__ void k_scan1(const int* __restrict__ cnt, int* __restrict__ off,
                        int* __restrict__ bsum, int n)
{
    __shared__ int sh[1024];
    int i = blockIdx.x * 1024 + threadIdx.x;
    int v = (i < n) ? cnt[i] : 0;
    sh[threadIdx.x] = v;
    __syncthreads();
    #pragma unroll
    for (int ofs = 1; ofs < 1024; ofs <<= 1) {
        int t = (threadIdx.x >= ofs) ? sh[threadIdx.x - ofs] : 0;
        __syncthreads();
        sh[threadIdx.x] += t;
        __syncthreads();
    }
    if (i < n) off[i] = sh[threadIdx.x] - v;
    if (threadIdx.x == 1023) bsum[blockIdx.x] = sh[1023];
}

__global__ void k_scan2(int* bsum, int nb) {
    __shared__ int sh[1024];
    int t = threadIdx.x;
    int v = (t < nb) ? bsum[t] : 0;
    sh[t] = v;
    __syncthreads();
    #pragma unroll
    for (int ofs = 1; ofs < 1024; ofs <<= 1) {
        int u = (t >= ofs) ? sh[t - ofs] : 0;
        __syncthreads();
        sh[t] += u;
        __syncthreads();
    }
    if (t < nb) bsum[t] = sh[t] - v;
}

__global__ void k_scan3_prep(int* __restrict__ off, const int* __restrict__ bsum,
                             const int* __restrict__ cnt, int* __restrict__ cursor,
                             float* __restrict__ invs, int N, int E)
{
    int i = blockIdx.x * 1024 + threadIdx.x;
    if (i < N) {
        int o = off[i] + bsum[blockIdx.x];
        off[i] = o;
        cursor[i] = o;
        invs[i] = rsqrtf((float)(cnt[i] + 1));
    }
    if (i == 0) off[N] = E;
}

__global__ void k_fill(const int* __restrict__ esrc, const int* __restrict__ edst,
                       const float* __restrict__ invs, int* cursor,
                       float2* __restrict__ edge, int E)
{
    int e = blockIdx.x * blockDim.x + threadIdx.x;
    if (e < E) {
        int d = edst[e];
        int s = esrc[e];
        int pos = atomicAdd(&cursor[d], 1);
        edge[pos] = make_float2(__int_as_float(s), invs[s]);
    }
}

// ---------------- weight folds (conv0 into encoder-gemm2) ----------------
__global__ void k_wfold(const float* __restrict__ w2, const float* __restrict__ cw0,
                        float* __restrict__ wf)
{
    __shared__ float row[128];
    int k = blockIdx.x, n = threadIdx.x;
    row[n] = w2[k * 128 + n];
    __syncthreads();
    float acc = 0.f;
    #pragma unroll 8
    for (int j = 0; j < 128; ++j) acc = fmaf(row[j], cw0[j * 128 + n], acc);
    wf[k * 128 + n] = acc;
}

__global__ void k_bfold(const float* __restrict__ b2, const float* __restrict__ cw0,
                        const float* __restrict__ cb0, float* __restrict__ bf)
{
    int n = threadIdx.x;
    float acc = cb0[n];
    #pragma unroll 8
    for (int j = 0; j < 128; ++j) acc = fmaf(b2[j], cw0[j * 128 + n], acc);
    bf[n] = acc;
}

// ---------------- persistent tf32 GEMM (round-8, proven) ----------------
__global__ void __launch_bounds__(256, 2)
gemm_tf32p(const float* __restrict__ A, const float* __restrict__ W,
           const float* __restrict__ bias, float* __restrict__ C,
           int M, int ntiles, int reluA)
{
    extern __shared__ char smem_raw[];
    uint4* Wf = (uint4*)smem_raw;                    // [16ks][8ntp][32lane] = 64KB
    float* As = (float*)(smem_raw + 65536);          // [PTILE][ASTRIDE]
    const int tid = threadIdx.x;

    auto prefetch = [&](int tileIdx) {
        if (tileIdx < ntiles) {
            int row0 = tileIdx * PTILE;
            #pragma unroll
            for (int j = 0; j < 8; ++j) {
                int cid = tid + 256 * j;
                int row = cid >> 5;
                int c16 = cid & 31;
                const float* gsrc = A + (size_t)(row0 + row) * 128 + c16 * 4;
                float* dptr = As + row * ASTRIDE + c16 * 4;
                unsigned sa = (unsigned)__cvta_generic_to_shared(dptr);
                int sz = (row0 + row < M) ? 16 : 0;
                if (sz == 0) gsrc = A;
                asm volatile("cp.async.ca.shared.global [%0], [%1], 16, %2;"
                             :: "r"(sa), "l"(gsrc), "r"(sz));
            }
        }
        asm volatile("cp.async.commit_group;");
    };

    prefetch(blockIdx.x);

    for (int i = tid * 4; i < 128 * 128; i += 256 * 4) {
        int k = i >> 7, n0 = i & 127;
        float4 v = *(const float4*)(W + i);
        int ks = k >> 3, r = k & 7, reg = r >> 2, tg = r & 3;
        #pragma unroll
        for (int j = 0; j < 4; ++j) {
            int n = n0 + j;
            int nt = n >> 3, gd = n & 7;
            int ntp = nt >> 1, half = nt & 1;
            unsigned* p = (unsigned*)&Wf[(ks * 8 + ntp) * 32 + ((gd << 2) | tg)];
            p[half * 2 + reg] = f2tf32((&v.x)[j]);
        }
    }

    const int warp = tid >> 5;
    const int lane = tid & 31;
    const int gid  = lane >> 2;
    const int tig  = lane & 3;
    const int wm   = warp & 1;
    const int wn   = warp >> 1;

    const int quad = lane >> 3;
    const int qr   = lane & 7;
    unsigned abase[2];
    #pragma unroll
    for (int mi = 0; mi < 2; ++mi) {
        float* p = As + (wm * 32 + mi * 16 + (quad & 1) * 8 + qr) * ASTRIDE + (quad >> 1) * 4;
        abase[mi] = (unsigned)__cvta_generic_to_shared(p);
    }

    for (int tile = blockIdx.x; tile < ntiles; tile += gridDim.x) {
        asm volatile("cp.async.wait_group 0;");
        __syncthreads();

        #pragma unroll
        for (int j = 0; j < 8; ++j) {
            int cid = tid + 256 * j;
            int row = cid >> 5;
            int c16 = cid & 31;
            float4* p = (float4*)(As + row * ASTRIDE + c16 * 4);
            float4 v = *p;
            if (reluA) {
                v.x = fmaxf(v.x, 0.f); v.y = fmaxf(v.y, 0.f);
                v.z = fmaxf(v.z, 0.f); v.w = fmaxf(v.w, 0.f);
            }
            uint4 u;
            u.x = f2tf32(v.x); u.y = f2tf32(v.y); u.z = f2tf32(v.z); u.w = f2tf32(v.w);
            *(uint4*)p = u;
        }
        __syncthreads();

        float acc[2][4][4];
        #pragma unroll
        for (int mi = 0; mi < 2; ++mi)
            #pragma unroll
            for (int t = 0; t < 4; ++t)
                #pragma unroll
                for (int c = 0; c < 4; ++c) acc[mi][t][c] = 0.f;

        #pragma unroll
        for (int ks = 0; ks < 16; ++ks) {
            unsigned au[2][4];
            #pragma unroll
            for (int mi = 0; mi < 2; ++mi) {
                asm volatile(
                    "ldmatrix.sync.aligned.m8n8.x4.shared.b16 {%0,%1,%2,%3}, [%4];"
                    : "=r"(au[mi][0]), "=r"(au[mi][1]), "=r"(au[mi][2]), "=r"(au[mi][3])
                    : "r"(abase[mi] + ks * 32));
            }
            const uint4* Bp = Wf + (ks * 8 + wn * 2) * 32 + lane;
            #pragma unroll
            for (int tp = 0; tp < 2; ++tp) {
                uint4 b4 = Bp[tp * 32];
                #pragma unroll
                for (int mi = 0; mi < 2; ++mi) {
                    asm volatile(
                        "mma.sync.aligned.m16n8k8.row.col.f32.tf32.tf32.f32 "
                        "{%0,%1,%2,%3}, {%4,%5,%6,%7}, {%8,%9}, {%0,%1,%2,%3};"
                        : "+f"(acc[mi][tp * 2][0]), "+f"(acc[mi][tp * 2][1]),
                          "+f"(acc[mi][tp * 2][2]), "+f"(acc[mi][tp * 2][3])
                        : "r"(au[mi][0]), "r"(au[mi][1]), "r"(au[mi][2]), "r"(au[mi][3]),
                          "r"(b4.x), "r"(b4.y));
                    asm volatile(
                        "mma.sync.aligned.m16n8k8.row.col.f32.tf32.tf32.f32 "
                        "{%0,%1,%2,%3}, {%4,%5,%6,%7}, {%8,%9}, {%0,%1,%2,%3};"
                        : "+f"(acc[mi][tp * 2 + 1][0]), "+f"(acc[mi][tp * 2 + 1][1]),
                          "+f"(acc[mi][tp * 2 + 1][2]), "+f"(acc[mi][tp * 2 + 1][3])
                        : "r"(au[mi][0]), "r"(au[mi][1]), "r"(au[mi][2]), "r"(au[mi][3]),
                          "r"(b4.z), "r"(b4.w));
                }
            }
        }

        __syncthreads();
        prefetch(tile + gridDim.x);

        const int rbase = tile * PTILE + wm * 32;
        #pragma unroll
        for (int mi = 0; mi < 2; ++mi) {
            const int rA = rbase + mi * 16 + gid;
            const int rB = rA + 8;
            #pragma unroll
            for (int t = 0; t < 4; ++t) {
                int n = (wn * 4 + t) * 8 + tig * 2;
                float2 b = *(const float2*)(bias + n);
                if (rA < M)
                    *(float2*)(C + (size_t)rA * 128 + n) =
                        make_float2(acc[mi][t][0] + b.x, acc[mi][t][1] + b.y);
                if (rB < M)
                    *(float2*)(C + (size_t)rB * 128 + n) =
                        make_float2(acc[mi][t][2] + b.x, acc[mi][t][3] + b.y);
            }
        }
    }
}

// ---------------- CSR gather aggregation (round-8 body, optional relu at store) ----------------
__global__ void k_aggregate(const float* __restrict__ hw, const float2* __restrict__ edge,
                            const int* __restrict__ off, const float* __restrict__ invs,
                            float* __restrict__ out, int N, int reluStore)
{
    int w = (blockIdx.x * blockDim.x + threadIdx.x) >> 5;
    if (w >= N) return;
    int lane = threadIdx.x & 31;
    int beg = __ldg(off + w), end = __ldg(off + w + 1);
    float invd = __ldg(invs + w);
    const float4* hw4 = (const float4*)hw;

    float4 s = __ldg(hw4 + (size_t)w * 32 + lane);
    float4 a0 = make_float4(s.x * invd, s.y * invd, s.z * invd, s.w * invd);
    float4 a1 = make_float4(0.f, 0.f, 0.f, 0.f);
    float4 a2 = make_float4(0.f, 0.f, 0.f, 0.f);
    float4 a3 = make_float4(0.f, 0.f, 0.f, 0.f);

    int j = beg;
    for (; j + 4 <= end; j += 4) {
        float2 e0 = __ldg(edge + j);
        float2 e1 = __ldg(edge + j + 1);
        float2 e2 = __ldg(edge + j + 2);
        float2 e3 = __ldg(edge + j + 3);
        float4 v0 = __ldg(hw4 + (size_t)__float_as_int(e0.x) * 32 + lane);
        float4 v1 = __ldg(hw4 + (size_t)__float_as_int(e1.x) * 32 + lane);
        float4 v2 = __ldg(hw4 + (size_t)__float_as_int(e2.x) * 32 + lane);
        float4 v3 = __ldg(hw4 + (size_t)__float_as_int(e3.x) * 32 + lane);
        a0.x = fmaf(v0.x, e0.y, a0.x); a0.y = fmaf(v0.y, e0.y, a0.y);
        a0.z = fmaf(v0.z, e0.y, a0.z); a0.w = fmaf(v0.w, e0.y, a0.w);
        a1.x = fmaf(v1.x, e1.y, a1.x); a1.y = fmaf(v1.y, e1.y, a1.y);
        a1.z = fmaf(v1.z, e1.y, a1.z); a1.w = fmaf(v1.w, e1.y, a1.w);
        a2.x = fmaf(v2.x, e2.y, a2.x); a2.y = fmaf(v2.y, e2.y, a2.y);
        a2.z = fmaf(v2.z, e2.y, a2.z); a2.w = fmaf(v2.w, e2.y, a2.w);
        a3.x = fmaf(v3.x, e3.y, a3.x); a3.y = fmaf(v3.y, e3.y, a3.y);
        a3.z = fmaf(v3.z, e3.y, a3.z); a3.w = fmaf(v3.w, e3.y, a3.w);
    }
    for (; j < end; ++j) {
        float2 e0 = __ldg(edge + j);
        float4 v0 = __ldg(hw4 + (size_t)__float_as_int(e0.x) * 32 + lane);
        a0.x = fmaf(v0.x, e0.y, a0.x); a0.y = fmaf(v0.y, e0.y, a0.y);
        a0.z = fmaf(v0.z, e0.y, a0.z); a0.w = fmaf(v0.w, e0.y, a0.w);
    }

    float4 o;
    o.x = ((a0.x + a1.x) + (a2.x + a3.x)) * invd;
    o.y = ((a0.y + a1.y) + (a2.y + a3.y)) * invd;
    o.z = ((a0.z + a1.z) + (a2.z + a3.z)) * invd;
    o.w = ((a0.w + a1.w) + (a2.w + a3.w)) * invd;
    if (reluStore) {
        o.x = fmaxf(o.x, 0.f); o.y = fmaxf(o.y, 0.f);
        o.z = fmaxf(o.z, 0.f); o.w = fmaxf(o.w, 0.f);
    }
    ((float4*)out)[(size_t)w * 32 + lane] = o;
}

// ---------------- last-layer aggregate with FUSED pooling ----------------
__global__ void k_aggregate2p(const float* __restrict__ hw, const float2* __restrict__ edge,
                              const int* __restrict__ off, const float* __restrict__ invs,
                              const int* __restrict__ batch, float* __restrict__ pooled,
                              float* __restrict__ poolscal, int N)
{
    int w = (blockIdx.x * blockDim.x + threadIdx.x) >> 5;
    if (w >= N) return;
    int lane = threadIdx.x & 31;
    int beg = __ldg(off + w), end = __ldg(off + w + 1);
    float invd = __ldg(invs + w);
    const float4* hw4 = (const float4*)hw;

    float4 s = __ldg(hw4 + (size_t)w * 32 + lane);
    float4 a0 = make_float4(s.x * invd, s.y * invd, s.z * invd, s.w * invd);
    float4 a1 = make_float4(0.f, 0.f, 0.f, 0.f);
    float4 a2 = make_float4(0.f, 0.f, 0.f, 0.f);
    float4 a3 = make_float4(0.f, 0.f, 0.f, 0.f);
    float esum = 0.f;

    int j = beg;
    for (; j + 4 <= end; j += 4) {
        float2 e0 = __ldg(edge + j);
        float2 e1 = __ldg(edge + j + 1);
        float2 e2 = __ldg(edge + j + 2);
        float2 e3 = __ldg(edge + j + 3);
        float4 v0 = __ldg(hw4 + (size_t)__float_as_int(e0.x) * 32 + lane);
        float4 v1 = __ldg(hw4 + (size_t)__float_as_int(e1.x) * 32 + lane);
        float4 v2 = __ldg(hw4 + (size_t)__float_as_int(e2.x) * 32 + lane);
        float4 v3 = __ldg(hw4 + (size_t)__float_as_int(e3.x) * 32 + lane);
        esum += (e0.y + e1.y) + (e2.y + e3.y);
        a0.x = fmaf(v0.x, e0.y, a0.x); a0.y = fmaf(v0.y, e0.y, a0.y);
        a0.z = fmaf(v0.z, e0.y, a0.z); a0.w = fmaf(v0.w, e0.y, a0.w);
        a1.x = fmaf(v1.x, e1.y, a1.x); a1.y = fmaf(v1.y, e1.y, a1.y);
        a1.z = fmaf(v1.z, e1.y, a1.z); a1.w = fmaf(v1.w, e1.y, a1.w);
        a2.x = fmaf(v2.x, e2.y, a2.x); a2.y = fmaf(v2.y, e2.y, a2.y);
        a2.z = fmaf(v2.z, e2.y, a2.z); a2.w = fmaf(v2.w, e2.y, a2.w);
        a3.x = fmaf(v3.x, e3.y, a3.x); a3.y = fmaf(v3.y, e3.y, a3.y);
        a3.z = fmaf(v3.z, e3.y, a3.z); a3.w = fmaf(v3.w, e3.y, a3.w);
    }
    for (; j < end; ++j) {
        float2 e0 = __ldg(edge + j);
        float4 v0 = __ldg(hw4 + (size_t)__float_as_int(e0.x) * 32 + lane);
        esum += e0.y;
        a0.x = fmaf(v0.x, e0.y, a0.x); a0.y = fmaf(v0.y, e0.y, a0.y);
        a0.z = fmaf(v0.z, e0.y, a0.z); a0.w = fmaf(v0.w, e0.y, a0.w);
    }

    float4 o;
    o.x = ((a0.x + a1.x) + (a2.x + a3.x)) * invd;
    o.y = ((a0.y + a1.y) + (a2.y + a3.y)) * invd;
    o.z = ((a0.z + a1.z) + (a2.z + a3.z)) * invd;
    o.w = ((a0.w + a1.w) + (a2.w + a3.w)) * invd;

    int g = __ldg(batch + w);
    float* p = pooled + (size_t)g * 128 + lane * 4;
    asm volatile("red.global.add.v4.f32 [%0], {%1,%2,%3,%4};"
                 :: "l"(p), "f"(o.x), "f"(o.y), "f"(o.z), "f"(o.w)
                 : "memory");
    if (lane == 0) {
        float sv = invd * (invd + esum);
        asm volatile("red.global.add.f32 [%0], %1;"
                     :: "l"(poolscal + g), "f"(sv) : "memory");
    }
}

// ---------------- decoder with folded conv2 ----------------
__global__ void k_decoder2(const float* __restrict__ pooledY, const float* __restrict__ poolscal,
                           const float* __restrict__ cw2, const float* __restrict__ cb2,
                           const float* __restrict__ w1, const float* __restrict__ b1,
                           const float* __restrict__ w2, const float* __restrict__ b2,
                           float* __restrict__ out)
{
    __shared__ float pY[128];
    __shared__ float p[128];
    __shared__ float d1[128];
    int g = blockIdx.x;
    int t = threadIdx.x;
    pY[t] = pooledY[g * 128 + t];
    __syncthreads();
    float ps = poolscal[g];
    float acc = ps * cb2[t];
    #pragma unroll 8
    for (int j = 0; j < 128; ++j) acc = fmaf(pY[j], cw2[j * 128 + t], acc);
    p[t] = acc;
    __syncthreads();
    float s = b1[t];
    #pragma unroll 8
    for (int k = 0; k < 128; ++k) s = fmaf(p[k], w1[k * 128 + t], s);
    d1[t] = fmaxf(s, 0.f);
    __syncthreads();
    if (t < 10) {
        float s2 = b2[t];
        #pragma unroll 8
        for (int j = 0; j < 128; ++j) s2 = fmaf(d1[j], w2[j * 10 + t], s2);
        out[g * 10 + t] = s2;
    }
}

// ---------------- driver: 1 side stream (round-13 proven envelope), folds first ----------------
extern "C" void kernel_launch(void* const* d_in, const int* in_sizes, int n_in,
                              void* d_out, int out_size)
{
    const float* x      = (const float*)d_in[0];
    const int*   ei     = (const int*)d_in[1];
    const int*   batch  = (const int*)d_in[3];
    const float* enc_w1 = (const float*)d_in[4];
    const float* enc_b1 = (const float*)d_in[5];
    const float* enc_w2 = (const float*)d_in[6];
    const float* enc_b2 = (const float*)d_in[7];
    const float* conv_w = (const float*)d_in[8];
    const float* conv_b = (const float*)d_in[9];
    const float* dec_w1 = (const float*)d_in[10];
    const float* dec_b1 = (const float*)d_in[11];
    const float* dec_w2 = (const float*)d_in[12];
    const float* dec_b2 = (const float*)d_in[13];

    const int N = in_sizes[0] / HDIM;
    const int E = in_sizes[1] / 2;
    const int G = out_size / 10;

    float *bufA, *bufB, *bufC, *invs, *pooled, *poolscal, *wfold, *bfold;
    int *cnt, *off, *cursor, *bsum;
    float2* edge;
    cudaGetSymbolAddress((void**)&bufA, g_bufA);
    cudaGetSymbolAddress((void**)&bufB, g_bufB);
    cudaGetSymbolAddress((void**)&bufC, g_bufC);
    cudaGetSymbolAddress((void**)&invs, g_invs);
    cudaGetSymbolAddress((void**)&pooled, g_pooled);
    cudaGetSymbolAddress((void**)&poolscal, g_poolscal);
    cudaGetSymbolAddress((void**)&wfold, g_wfold);
    cudaGetSymbolAddress((void**)&bfold, g_bfold);
    cudaGetSymbolAddress((void**)&cnt, g_cnt);
    cudaGetSymbolAddress((void**)&off, g_off);
    cudaGetSymbolAddress((void**)&cursor, g_cursor);
    cudaGetSymbolAddress((void**)&bsum, g_bsum);
    cudaGetSymbolAddress((void**)&edge, g_edge);

    const int* esrc = ei;
    const int* edst = ei + E;
    const int nb = (N + 1023) / 1024;
    const int ntiles = (N + PTILE - 1) / PTILE;

    const float* cw0 = conv_w;
    const float* cw1 = conv_w + 128 * 128;
    const float* cw2 = conv_w + 2 * 128 * 128;
    const float* cb0 = conv_b;
    const float* cb1 = conv_b + 128;
    const float* cb2 = conv_b + 2 * 128;

    cudaFuncSetAttribute(gemm_tf32p, cudaFuncAttributeMaxDynamicSharedMemorySize, GEMM_SMEM);

    // EXACTLY round-13's resource envelope: one side stream + three events
    cudaStream_t s2;
    cudaStreamCreateWithFlags(&s2, cudaStreamNonBlocking);
    cudaEvent_t evRoot, evW, evCSR;
    cudaEventCreateWithFlags(&evRoot, cudaEventDisableTiming);
    cudaEventCreateWithFlags(&evW, cudaEventDisableTiming);
    cudaEventCreateWithFlags(&evCSR, cudaEventDisableTiming);

    // fork s2 off the capture stream
    cudaEventRecord(evRoot, 0);
    cudaStreamWaitEvent(s2, evRoot, 0);

    // ---- s2: weight folds FIRST (3us) so GEMM2's gate clears early ----
    k_wfold<<<128, 128, 0, s2>>>(enc_w2, cw0, wfold);
    k_bfold<<<1, 128, 0, s2>>>(enc_b2, cw0, cb0, bfold);
    cudaEventRecord(evW, s2);

    // ---- s2: CSR build + edge fill (hidden under GEMM1+GEMM2) ----
    k_zeros<<<(N + 255) / 256, 256, 0, s2>>>(cnt, pooled, poolscal, N, G * 128, G);
    k_hist<<<(E + 255) / 256, 256, 0, s2>>>(edst, cnt, E);
    k_scan1<<<nb, 1024, 0, s2>>>(cnt, off, bsum, N);
    k_scan2<<<1, 1024, 0, s2>>>(bsum, nb);
    k_scan3_prep<<<nb, 1024, 0, s2>>>(off, bsum, cnt, cursor, invs, N, E);
    k_fill<<<(E + 255) / 256, 256, 0, s2>>>(esrc, edst, invs, cursor, edge, E);
    cudaEventRecord(evCSR, s2);

    // ---- main: encoder GEMM1 (concurrent with s2 chain) ----
    gemm_tf32p<<<GEMM_GRID, 256, GEMM_SMEM>>>(x, enc_w1, enc_b1, bufC, N, ntiles, 0);

    // encoder GEMM2 with conv0 folded: hw0 = relu(bufC)@wfold + bfold
    cudaStreamWaitEvent(0, evW, 0);
    gemm_tf32p<<<GEMM_GRID, 256, GEMM_SMEM>>>(bufC, wfold, bfold, bufB, N, ntiles, 1);

    // join CSR: aggregates need edge/off/invs
    cudaStreamWaitEvent(0, evCSR, 0);

    // layer 0 aggregate: h1_pre = Â hw0
    k_aggregate<<<(N * 32 + 255) / 256, 256>>>(bufB, edge, off, invs, bufA, N, 0);

    // layer 1: hw1 = relu(h1_pre)@cw1 + cb1 ; h2 = relu(Â hw1)
    gemm_tf32p<<<GEMM_GRID, 256, GEMM_SMEM>>>(bufA, cw1, cb1, bufB, N, ntiles, 1);
    k_aggregate<<<(N * 32 + 255) / 256, 256>>>(bufB, edge, off, invs, bufC, N, 1);

    // layer 2 folded + fused pooling
    k_aggregate2p<<<(N * 32 + 255) / 256, 256>>>(bufC, edge, off, invs,
                                                 batch, pooled, poolscal, N);

    // decoder with pf = pooled@cw2 + poolscal*cb2
    k_decoder2<<<G, 128>>>(pooled, poolscal, cw2, cb2,
                           dec_w1, dec_b1, dec_w2, dec_b2, (float*)d_out);
}